// round 1
// baseline (speedup 1.0000x reference)
#include <cuda_runtime.h>
#include <math.h>

#define B_SZ   16384
#define FDIM   2048
#define HID    256
#define NN     9
#define SDIM   (NN * HID)      // 2304
#define CATK   (2 * HID)       // 512
#define MROWS  (B_SZ * NN)     // 147456

#define BM 128
#define BN 128
#define BK 16
#define TM 8
#define TN 8

// ---------------- scratch (device globals: no allocation allowed) ----------------
__device__ float g_states_a[B_SZ * SDIM];   // 151 MB
__device__ float g_states_b[B_SZ * SDIM];   // 151 MB
__device__ float g_sbar[B_SZ * SDIM];       // 151 MB
__device__ float g_Wc[HID * CATK];          // [256, 512] = [U1 | U2@msg_w]
__device__ float g_b2[HID];                 // upd_b + U2 @ msg_b

// ---------------- prep: fold msg linear into update linear ----------------
// Wc[o][k]     = upd_w[o][k]                         (k < 256)
// Wc[o][256+k] = sum_m upd_w[o][256+m] * msg_w[m][k]
// b2[o]        = upd_b[o] + sum_m upd_w[o][256+m] * msg_b[m]
__global__ void prep_kernel(const float* __restrict__ msg_w,
                            const float* __restrict__ msg_b,
                            const float* __restrict__ upd_w,
                            const float* __restrict__ upd_b)
{
    int o = blockIdx.x;       // 0..255
    int k = threadIdx.x;      // 0..255
    const float* u2 = upd_w + o * CATK + HID;

    g_Wc[o * CATK + k] = upd_w[o * CATK + k];

    float acc = 0.f;
    #pragma unroll 4
    for (int m = 0; m < HID; ++m)
        acc += u2[m] * msg_w[m * HID + k];     // coalesced over k
    g_Wc[o * CATK + HID + k] = acc;

    if (k == 0) {
        float bb = upd_b[o];
        for (int m = 0; m < HID; ++m) bb += u2[m] * msg_b[m];
        g_b2[o] = bb;
    }
}

// ---------------- GEMM1: states = conc @ f2n_w^T + f2n_b + node encoder ----------------
// A: conc [16384, 2048] row-major. B: f2n_w [2304, 2048] row-major (out, in).
// C[b, j] -> g_states_a[b*2304 + j], j = n*256 + h
__global__ __launch_bounds__(256, 2)
void gemm1_kernel(const float* __restrict__ A,
                  const float* __restrict__ Bw,
                  const float* __restrict__ f2n_b,
                  const float* __restrict__ logits,   // [B, 9]
                  const float* __restrict__ enc_w,    // [256]
                  const float* __restrict__ enc_b,    // [256]
                  float* __restrict__ C)
{
    __shared__ float As[BK][BM + 4];
    __shared__ float Bs[BK][BN + 4];

    const int tid = threadIdx.x;
    const int m0  = blockIdx.y * BM;
    const int n0  = blockIdx.x * BN;

    const int lr0 = tid >> 2;            // 0..63
    const int lk0 = (tid & 3) << 2;      // 0,4,8,12
    const int lr1 = lr0 + 64;
    const int ty  = tid >> 4;            // 0..15
    const int tx  = tid & 15;            // 0..15

    const float* Ab = A  + (size_t)m0 * FDIM;
    const float* Bb = Bw + (size_t)n0 * FDIM;

    float acc[TM][TN];
    #pragma unroll
    for (int i = 0; i < TM; ++i)
        #pragma unroll
        for (int j = 0; j < TN; ++j) acc[i][j] = 0.f;

    float4 pa0 = *(const float4*)(Ab + (size_t)lr0 * FDIM + lk0);
    float4 pa1 = *(const float4*)(Ab + (size_t)lr1 * FDIM + lk0);
    float4 pb0 = *(const float4*)(Bb + (size_t)lr0 * FDIM + lk0);
    float4 pb1 = *(const float4*)(Bb + (size_t)lr1 * FDIM + lk0);

    for (int k0 = 0; k0 < FDIM; k0 += BK) {
        As[lk0+0][lr0]=pa0.x; As[lk0+1][lr0]=pa0.y; As[lk0+2][lr0]=pa0.z; As[lk0+3][lr0]=pa0.w;
        As[lk0+0][lr1]=pa1.x; As[lk0+1][lr1]=pa1.y; As[lk0+2][lr1]=pa1.z; As[lk0+3][lr1]=pa1.w;
        Bs[lk0+0][lr0]=pb0.x; Bs[lk0+1][lr0]=pb0.y; Bs[lk0+2][lr0]=pb0.z; Bs[lk0+3][lr0]=pb0.w;
        Bs[lk0+0][lr1]=pb1.x; Bs[lk0+1][lr1]=pb1.y; Bs[lk0+2][lr1]=pb1.z; Bs[lk0+3][lr1]=pb1.w;
        __syncthreads();

        int kn = k0 + BK;
        if (kn < FDIM) {
            pa0 = *(const float4*)(Ab + (size_t)lr0 * FDIM + kn + lk0);
            pa1 = *(const float4*)(Ab + (size_t)lr1 * FDIM + kn + lk0);
            pb0 = *(const float4*)(Bb + (size_t)lr0 * FDIM + kn + lk0);
            pb1 = *(const float4*)(Bb + (size_t)lr1 * FDIM + kn + lk0);
        }

        #pragma unroll
        for (int kk = 0; kk < BK; ++kk) {
            float4 av0 = *(const float4*)(&As[kk][ty * TM]);
            float4 av1 = *(const float4*)(&As[kk][ty * TM + 4]);
            float4 bv0 = *(const float4*)(&Bs[kk][tx * TN]);
            float4 bv1 = *(const float4*)(&Bs[kk][tx * TN + 4]);
            float a[TM] = {av0.x, av0.y, av0.z, av0.w, av1.x, av1.y, av1.z, av1.w};
            float b[TN] = {bv0.x, bv0.y, bv0.z, bv0.w, bv1.x, bv1.y, bv1.z, bv1.w};
            #pragma unroll
            for (int i = 0; i < TM; ++i)
                #pragma unroll
                for (int j = 0; j < TN; ++j)
                    acc[i][j] += a[i] * b[j];
        }
        __syncthreads();
    }

    // epilogue: + f2n_b[col] + enc_b[h] + logits[row, n] * enc_w[h]
    const int nblk  = n0 >> 8;                 // node index (constant per block)
    const int cbase = n0 + tx * TN;
    const int hbase = cbase & 255;
    #pragma unroll
    for (int i = 0; i < TM; ++i) {
        int row = m0 + ty * TM + i;
        float lg = logits[row * NN + nblk];
        float* crow = C + (size_t)row * SDIM + cbase;
        #pragma unroll
        for (int j0 = 0; j0 < TN; j0 += 4) {
            float4 fb = *(const float4*)(f2n_b + cbase + j0);
            float4 eb = *(const float4*)(enc_b + hbase + j0);
            float4 ew = *(const float4*)(enc_w + hbase + j0);
            float4 v;
            v.x = acc[i][j0+0] + fb.x + eb.x + lg * ew.x;
            v.y = acc[i][j0+1] + fb.y + eb.y + lg * ew.y;
            v.z = acc[i][j0+2] + fb.z + eb.z + lg * ew.z;
            v.w = acc[i][j0+3] + fb.w + eb.w + lg * ew.w;
            *(float4*)(crow + j0) = v;
        }
    }
}

// ---------------- adjacency aggregate: s̄[b,i,:] = sum_j A[i,j] s[b,j,:] ----------------
__device__ __forceinline__ float4 f4add(float4 a, float4 b) {
    return make_float4(a.x+b.x, a.y+b.y, a.z+b.z, a.w+b.w);
}
__device__ __forceinline__ float4 f4sub(float4 a, float4 b) {
    return make_float4(a.x-b.x, a.y-b.y, a.z-b.z, a.w-b.w);
}
__device__ __forceinline__ float4 f4scale(float4 a, float s) {
    return make_float4(a.x*s, a.y*s, a.z*s, a.w*s);
}

__global__ void sbar_kernel(const float* __restrict__ S, float* __restrict__ SB)
{
    int idx = blockIdx.x * blockDim.x + threadIdx.x;   // over B*64 float4 lanes
    if (idx >= B_SZ * 64) return;
    int b  = idx >> 6;
    int h4 = (idx & 63);                               // float4 index within 256 floats
    const float4* sp = (const float4*)(S + (size_t)b * SDIM) + h4;
    float4 s[NN];
    #pragma unroll
    for (int j = 0; j < NN; ++j) s[j] = sp[j * 64];
    float4 tot = s[0];
    #pragma unroll
    for (int j = 1; j < NN; ++j) tot = f4add(tot, s[j]);

    float4* op = (float4*)(SB + (size_t)b * SDIM) + h4;
    float4 m78 = f4scale(f4sub(tot, s[1]), 0.125f);
    op[0 * 64] = f4scale(tot, 1.f / 9.f);
    op[1 * 64] = f4scale(f4add(s[0], s[1]), 0.5f);
    float4 hub = f4add(s[0], f4add(s[7], s[8]));
    #pragma unroll
    for (int j = 2; j <= 6; ++j)
        op[j * 64] = f4scale(f4add(hub, s[j]), 0.25f);
    op[7 * 64] = m78;
    op[8 * 64] = m78;
}

// ---------------- step GEMM: new = tanh([S | SB] @ Wc^T + b2) ----------------
// A rows: MROWS, K = 512 (first 256 from S, last 256 from SB). B: g_Wc [256, 512].
__global__ __launch_bounds__(256, 2)
void step_gemm(const float* __restrict__ S,
               const float* __restrict__ SB,
               float* __restrict__ O)
{
    __shared__ float As[BK][BM + 4];
    __shared__ float Bs[BK][BN + 4];

    const int tid = threadIdx.x;
    const int m0  = blockIdx.y * BM;
    const int n0  = blockIdx.x * BN;

    const int lr0 = tid >> 2;
    const int lk0 = (tid & 3) << 2;
    const int lr1 = lr0 + 64;
    const int ty  = tid >> 4;
    const int tx  = tid & 15;

    float acc[TM][TN];
    #pragma unroll
    for (int i = 0; i < TM; ++i)
        #pragma unroll
        for (int j = 0; j < TN; ++j) acc[i][j] = 0.f;

    const float* Wc = g_Wc;

    // prefetch k0 = 0 (src = S)
    float4 pa0 = *(const float4*)(S + (size_t)(m0 + lr0) * HID + lk0);
    float4 pa1 = *(const float4*)(S + (size_t)(m0 + lr1) * HID + lk0);
    float4 pb0 = *(const float4*)(Wc + (size_t)(n0 + lr0) * CATK + lk0);
    float4 pb1 = *(const float4*)(Wc + (size_t)(n0 + lr1) * CATK + lk0);

    for (int k0 = 0; k0 < CATK; k0 += BK) {
        As[lk0+0][lr0]=pa0.x; As[lk0+1][lr0]=pa0.y; As[lk0+2][lr0]=pa0.z; As[lk0+3][lr0]=pa0.w;
        As[lk0+0][lr1]=pa1.x; As[lk0+1][lr1]=pa1.y; As[lk0+2][lr1]=pa1.z; As[lk0+3][lr1]=pa1.w;
        Bs[lk0+0][lr0]=pb0.x; Bs[lk0+1][lr0]=pb0.y; Bs[lk0+2][lr0]=pb0.z; Bs[lk0+3][lr0]=pb0.w;
        Bs[lk0+0][lr1]=pb1.x; Bs[lk0+1][lr1]=pb1.y; Bs[lk0+2][lr1]=pb1.z; Bs[lk0+3][lr1]=pb1.w;
        __syncthreads();

        int kn = k0 + BK;
        if (kn < CATK) {
            const float* srcn = (kn < HID) ? S : SB;
            int kcn = kn & (HID - 1);
            pa0 = *(const float4*)(srcn + (size_t)(m0 + lr0) * HID + kcn + lk0);
            pa1 = *(const float4*)(srcn + (size_t)(m0 + lr1) * HID + kcn + lk0);
            pb0 = *(const float4*)(Wc + (size_t)(n0 + lr0) * CATK + kn + lk0);
            pb1 = *(const float4*)(Wc + (size_t)(n0 + lr1) * CATK + kn + lk0);
        }

        #pragma unroll
        for (int kk = 0; kk < BK; ++kk) {
            float4 av0 = *(const float4*)(&As[kk][ty * TM]);
            float4 av1 = *(const float4*)(&As[kk][ty * TM + 4]);
            float4 bv0 = *(const float4*)(&Bs[kk][tx * TN]);
            float4 bv1 = *(const float4*)(&Bs[kk][tx * TN + 4]);
            float a[TM] = {av0.x, av0.y, av0.z, av0.w, av1.x, av1.y, av1.z, av1.w};
            float b[TN] = {bv0.x, bv0.y, bv0.z, bv0.w, bv1.x, bv1.y, bv1.z, bv1.w};
            #pragma unroll
            for (int i = 0; i < TM; ++i)
                #pragma unroll
                for (int j = 0; j < TN; ++j)
                    acc[i][j] += a[i] * b[j];
        }
        __syncthreads();
    }

    const int cbase = n0 + tx * TN;
    #pragma unroll
    for (int i = 0; i < TM; ++i) {
        int row = m0 + ty * TM + i;
        float* orow = O + (size_t)row * HID + cbase;
        #pragma unroll
        for (int j0 = 0; j0 < TN; j0 += 4) {
            float4 bb = *(const float4*)(g_b2 + cbase + j0);
            float4 v;
            v.x = tanhf(acc[i][j0+0] + bb.x);
            v.y = tanhf(acc[i][j0+1] + bb.y);
            v.z = tanhf(acc[i][j0+2] + bb.z);
            v.w = tanhf(acc[i][j0+3] + bb.w);
            *(float4*)(orow + j0) = v;
        }
    }
}

// ---------------- output head: nodes 7 and 8 ----------------
__global__ void out_kernel(const float* __restrict__ S,
                           const float* __restrict__ out_w,
                           const float* __restrict__ out_b,
                           float* __restrict__ out)
{
    int gwarp = (blockIdx.x * blockDim.x + threadIdx.x) >> 5;
    int lane  = threadIdx.x & 31;
    if (gwarp >= B_SZ) return;
    const float* s7 = S + (size_t)gwarp * SDIM + 7 * HID;
    float v7 = 0.f, v8 = 0.f;
    #pragma unroll
    for (int h = lane; h < HID; h += 32) {
        float w = out_w[h];
        v7 += s7[h] * w;
        v8 += s7[HID + h] * w;
    }
    #pragma unroll
    for (int o = 16; o; o >>= 1) {
        v7 += __shfl_xor_sync(0xFFFFFFFFu, v7, o);
        v8 += __shfl_xor_sync(0xFFFFFFFFu, v8, o);
    }
    if (lane == 0) {
        float b = out_b[0];
        out[gwarp]        = v7 + b;   // logits_chronic  (node 7)
        out[B_SZ + gwarp] = v8 + b;   // logits_acute_and_chronic (node 8)
    }
}

// ---------------- launch ----------------
extern "C" void kernel_launch(void* const* d_in, const int* in_sizes, int n_in,
                              void* d_out, int out_size)
{
    (void)in_sizes; (void)n_in; (void)out_size;
    const float* conc   = (const float*)d_in[0];
    const float* logits = (const float*)d_in[1];
    const float* enc_w  = (const float*)d_in[2];
    const float* enc_b  = (const float*)d_in[3];
    const float* f2n_w  = (const float*)d_in[4];
    const float* f2n_b  = (const float*)d_in[5];
    const float* msg_w  = (const float*)d_in[6];
    const float* msg_b  = (const float*)d_in[7];
    const float* upd_w  = (const float*)d_in[8];
    const float* upd_b  = (const float*)d_in[9];
    const float* out_w  = (const float*)d_in[10];
    const float* out_b  = (const float*)d_in[11];
    float* out = (float*)d_out;

    float *sa = nullptr, *sb = nullptr, *sbar = nullptr;
    cudaGetSymbolAddress((void**)&sa,   g_states_a);
    cudaGetSymbolAddress((void**)&sb,   g_states_b);
    cudaGetSymbolAddress((void**)&sbar, g_sbar);

    // 1) fold msg linear into update linear
    prep_kernel<<<HID, HID>>>(msg_w, msg_b, upd_w, upd_b);

    // 2) big feature GEMM + node-encoder init -> states_a
    {
        dim3 grid(SDIM / BN, B_SZ / BM);   // (18, 128)
        gemm1_kernel<<<grid, 256>>>(conc, f2n_w, f2n_b, logits, enc_w, enc_b, sa);
    }

    // 3) 4 GNN steps (ping-pong a <-> b)
    float* cur = sa;
    float* nxt = sb;
    for (int step = 0; step < 4; ++step) {
        sbar_kernel<<<(B_SZ * 64) / 256, 256>>>(cur, sbar);
        dim3 grid(HID / BN, MROWS / BM);   // (2, 1152)
        step_gemm<<<grid, 256>>>(cur, sbar, nxt);
        float* t = cur; cur = nxt; nxt = t;
    }
    // after 4 steps, final states are in `cur` (== states_a)

    // 4) output head
    out_kernel<<<B_SZ / 8, 256>>>(cur, out_w, out_b, out);
}

// round 2
// speedup vs baseline: 1.0001x; 1.0001x over previous
#include <cuda_runtime.h>
#include <math.h>

#define B_SZ   16384
#define FDIM   2048
#define HID    256
#define NN     9
#define SDIM   (NN * HID)      // 2304
#define CATK   (2 * HID)       // 512
#define MROWS  (B_SZ * NN)     // 147456

#define BM 128
#define BN 128
#define BK 16
#define TM 8
#define TN 8

// ---------------- scratch (device globals: no allocation allowed) ----------------
__device__ float g_states_a[B_SZ * SDIM];   // 151 MB
__device__ float g_states_b[B_SZ * SDIM];   // 151 MB
__device__ float g_sbar[B_SZ * SDIM];       // 151 MB
__device__ float g_Wc[HID * CATK];          // [256, 512] = [U1 | U2@msg_w]
__device__ float g_b2[HID];                 // upd_b + U2 @ msg_b

// ---------------- prep: fold msg linear into update linear ----------------
// Wc[o][k]     = upd_w[o][k]                         (k < 256)
// Wc[o][256+k] = sum_m upd_w[o][256+m] * msg_w[m][k]
// b2[o]        = upd_b[o] + sum_m upd_w[o][256+m] * msg_b[m]
__global__ void prep_kernel(const float* __restrict__ msg_w,
                            const float* __restrict__ msg_b,
                            const float* __restrict__ upd_w,
                            const float* __restrict__ upd_b)
{
    int o = blockIdx.x;       // 0..255
    int k = threadIdx.x;      // 0..255
    const float* u2 = upd_w + o * CATK + HID;

    g_Wc[o * CATK + k] = upd_w[o * CATK + k];

    float acc = 0.f;
    #pragma unroll 4
    for (int m = 0; m < HID; ++m)
        acc += u2[m] * msg_w[m * HID + k];     // coalesced over k
    g_Wc[o * CATK + HID + k] = acc;

    if (k == 0) {
        float bb = upd_b[o];
        for (int m = 0; m < HID; ++m) bb += u2[m] * msg_b[m];
        g_b2[o] = bb;
    }
}

// ---------------- GEMM1: states = conc @ f2n_w^T + f2n_b + node encoder ----------------
// A: conc [16384, 2048] row-major. B: f2n_w [2304, 2048] row-major (out, in).
// C[b, j] -> g_states_a[b*2304 + j], j = n*256 + h
__global__ __launch_bounds__(256, 2)
void gemm1_kernel(const float* __restrict__ A,
                  const float* __restrict__ Bw,
                  const float* __restrict__ f2n_b,
                  const float* __restrict__ logits,   // [B, 9]
                  const float* __restrict__ enc_w,    // [256]
                  const float* __restrict__ enc_b,    // [256]
                  float* __restrict__ C)
{
    __shared__ float As[BK][BM + 4];
    __shared__ float Bs[BK][BN + 4];

    const int tid = threadIdx.x;
    const int m0  = blockIdx.y * BM;
    const int n0  = blockIdx.x * BN;

    const int lr0 = tid >> 2;            // 0..63
    const int lk0 = (tid & 3) << 2;      // 0,4,8,12
    const int lr1 = lr0 + 64;
    const int ty  = tid >> 4;            // 0..15
    const int tx  = tid & 15;            // 0..15

    const float* Ab = A  + (size_t)m0 * FDIM;
    const float* Bb = Bw + (size_t)n0 * FDIM;

    float acc[TM][TN];
    #pragma unroll
    for (int i = 0; i < TM; ++i)
        #pragma unroll
        for (int j = 0; j < TN; ++j) acc[i][j] = 0.f;

    float4 pa0 = *(const float4*)(Ab + (size_t)lr0 * FDIM + lk0);
    float4 pa1 = *(const float4*)(Ab + (size_t)lr1 * FDIM + lk0);
    float4 pb0 = *(const float4*)(Bb + (size_t)lr0 * FDIM + lk0);
    float4 pb1 = *(const float4*)(Bb + (size_t)lr1 * FDIM + lk0);

    for (int k0 = 0; k0 < FDIM; k0 += BK) {
        As[lk0+0][lr0]=pa0.x; As[lk0+1][lr0]=pa0.y; As[lk0+2][lr0]=pa0.z; As[lk0+3][lr0]=pa0.w;
        As[lk0+0][lr1]=pa1.x; As[lk0+1][lr1]=pa1.y; As[lk0+2][lr1]=pa1.z; As[lk0+3][lr1]=pa1.w;
        Bs[lk0+0][lr0]=pb0.x; Bs[lk0+1][lr0]=pb0.y; Bs[lk0+2][lr0]=pb0.z; Bs[lk0+3][lr0]=pb0.w;
        Bs[lk0+0][lr1]=pb1.x; Bs[lk0+1][lr1]=pb1.y; Bs[lk0+2][lr1]=pb1.z; Bs[lk0+3][lr1]=pb1.w;
        __syncthreads();

        int kn = k0 + BK;
        if (kn < FDIM) {
            pa0 = *(const float4*)(Ab + (size_t)lr0 * FDIM + kn + lk0);
            pa1 = *(const float4*)(Ab + (size_t)lr1 * FDIM + kn + lk0);
            pb0 = *(const float4*)(Bb + (size_t)lr0 * FDIM + kn + lk0);
            pb1 = *(const float4*)(Bb + (size_t)lr1 * FDIM + kn + lk0);
        }

        #pragma unroll
        for (int kk = 0; kk < BK; ++kk) {
            float4 av0 = *(const float4*)(&As[kk][ty * TM]);
            float4 av1 = *(const float4*)(&As[kk][ty * TM + 4]);
            float4 bv0 = *(const float4*)(&Bs[kk][tx * TN]);
            float4 bv1 = *(const float4*)(&Bs[kk][tx * TN + 4]);
            float a[TM] = {av0.x, av0.y, av0.z, av0.w, av1.x, av1.y, av1.z, av1.w};
            float b[TN] = {bv0.x, bv0.y, bv0.z, bv0.w, bv1.x, bv1.y, bv1.z, bv1.w};
            #pragma unroll
            for (int i = 0; i < TM; ++i)
                #pragma unroll
                for (int j = 0; j < TN; ++j)
                    acc[i][j] += a[i] * b[j];
        }
        __syncthreads();
    }

    // epilogue: + f2n_b[col] + enc_b[h] + logits[row, n] * enc_w[h]
    const int nblk  = n0 >> 8;                 // node index (constant per block)
    const int cbase = n0 + tx * TN;
    const int hbase = cbase & 255;
    #pragma unroll
    for (int i = 0; i < TM; ++i) {
        int row = m0 + ty * TM + i;
        float lg = logits[row * NN + nblk];
        float* crow = C + (size_t)row * SDIM + cbase;
        #pragma unroll
        for (int j0 = 0; j0 < TN; j0 += 4) {
            float4 fb = *(const float4*)(f2n_b + cbase + j0);
            float4 eb = *(const float4*)(enc_b + hbase + j0);
            float4 ew = *(const float4*)(enc_w + hbase + j0);
            float4 v;
            v.x = acc[i][j0+0] + fb.x + eb.x + lg * ew.x;
            v.y = acc[i][j0+1] + fb.y + eb.y + lg * ew.y;
            v.z = acc[i][j0+2] + fb.z + eb.z + lg * ew.z;
            v.w = acc[i][j0+3] + fb.w + eb.w + lg * ew.w;
            *(float4*)(crow + j0) = v;
        }
    }
}

// ---------------- adjacency aggregate: s̄[b,i,:] = sum_j A[i,j] s[b,j,:] ----------------
__device__ __forceinline__ float4 f4add(float4 a, float4 b) {
    return make_float4(a.x+b.x, a.y+b.y, a.z+b.z, a.w+b.w);
}
__device__ __forceinline__ float4 f4sub(float4 a, float4 b) {
    return make_float4(a.x-b.x, a.y-b.y, a.z-b.z, a.w-b.w);
}
__device__ __forceinline__ float4 f4scale(float4 a, float s) {
    return make_float4(a.x*s, a.y*s, a.z*s, a.w*s);
}

__global__ void sbar_kernel(const float* __restrict__ S, float* __restrict__ SB)
{
    int idx = blockIdx.x * blockDim.x + threadIdx.x;   // over B*64 float4 lanes
    if (idx >= B_SZ * 64) return;
    int b  = idx >> 6;
    int h4 = (idx & 63);                               // float4 index within 256 floats
    const float4* sp = (const float4*)(S + (size_t)b * SDIM) + h4;
    float4 s[NN];
    #pragma unroll
    for (int j = 0; j < NN; ++j) s[j] = sp[j * 64];
    float4 tot = s[0];
    #pragma unroll
    for (int j = 1; j < NN; ++j) tot = f4add(tot, s[j]);

    float4* op = (float4*)(SB + (size_t)b * SDIM) + h4;
    float4 m78 = f4scale(f4sub(tot, s[1]), 0.125f);
    op[0 * 64] = f4scale(tot, 1.f / 9.f);
    op[1 * 64] = f4scale(f4add(s[0], s[1]), 0.5f);
    float4 hub = f4add(s[0], f4add(s[7], s[8]));
    #pragma unroll
    for (int j = 2; j <= 6; ++j)
        op[j * 64] = f4scale(f4add(hub, s[j]), 0.25f);
    op[7 * 64] = m78;
    op[8 * 64] = m78;
}

// ---------------- step GEMM: new = tanh([S | SB] @ Wc^T + b2) ----------------
// A rows: MROWS, K = 512 (first 256 from S, last 256 from SB). B: g_Wc [256, 512].
__global__ __launch_bounds__(256, 2)
void step_gemm(const float* __restrict__ S,
               const float* __restrict__ SB,
               float* __restrict__ O)
{
    __shared__ float As[BK][BM + 4];
    __shared__ float Bs[BK][BN + 4];

    const int tid = threadIdx.x;
    const int m0  = blockIdx.y * BM;
    const int n0  = blockIdx.x * BN;

    const int lr0 = tid >> 2;
    const int lk0 = (tid & 3) << 2;
    const int lr1 = lr0 + 64;
    const int ty  = tid >> 4;
    const int tx  = tid & 15;

    float acc[TM][TN];
    #pragma unroll
    for (int i = 0; i < TM; ++i)
        #pragma unroll
        for (int j = 0; j < TN; ++j) acc[i][j] = 0.f;

    const float* Wc = g_Wc;

    // prefetch k0 = 0 (src = S)
    float4 pa0 = *(const float4*)(S + (size_t)(m0 + lr0) * HID + lk0);
    float4 pa1 = *(const float4*)(S + (size_t)(m0 + lr1) * HID + lk0);
    float4 pb0 = *(const float4*)(Wc + (size_t)(n0 + lr0) * CATK + lk0);
    float4 pb1 = *(const float4*)(Wc + (size_t)(n0 + lr1) * CATK + lk0);

    for (int k0 = 0; k0 < CATK; k0 += BK) {
        As[lk0+0][lr0]=pa0.x; As[lk0+1][lr0]=pa0.y; As[lk0+2][lr0]=pa0.z; As[lk0+3][lr0]=pa0.w;
        As[lk0+0][lr1]=pa1.x; As[lk0+1][lr1]=pa1.y; As[lk0+2][lr1]=pa1.z; As[lk0+3][lr1]=pa1.w;
        Bs[lk0+0][lr0]=pb0.x; Bs[lk0+1][lr0]=pb0.y; Bs[lk0+2][lr0]=pb0.z; Bs[lk0+3][lr0]=pb0.w;
        Bs[lk0+0][lr1]=pb1.x; Bs[lk0+1][lr1]=pb1.y; Bs[lk0+2][lr1]=pb1.z; Bs[lk0+3][lr1]=pb1.w;
        __syncthreads();

        int kn = k0 + BK;
        if (kn < CATK) {
            const float* srcn = (kn < HID) ? S : SB;
            int kcn = kn & (HID - 1);
            pa0 = *(const float4*)(srcn + (size_t)(m0 + lr0) * HID + kcn + lk0);
            pa1 = *(const float4*)(srcn + (size_t)(m0 + lr1) * HID + kcn + lk0);
            pb0 = *(const float4*)(Wc + (size_t)(n0 + lr0) * CATK + kn + lk0);
            pb1 = *(const float4*)(Wc + (size_t)(n0 + lr1) * CATK + kn + lk0);
        }

        #pragma unroll
        for (int kk = 0; kk < BK; ++kk) {
            float4 av0 = *(const float4*)(&As[kk][ty * TM]);
            float4 av1 = *(const float4*)(&As[kk][ty * TM + 4]);
            float4 bv0 = *(const float4*)(&Bs[kk][tx * TN]);
            float4 bv1 = *(const float4*)(&Bs[kk][tx * TN + 4]);
            float a[TM] = {av0.x, av0.y, av0.z, av0.w, av1.x, av1.y, av1.z, av1.w};
            float b[TN] = {bv0.x, bv0.y, bv0.z, bv0.w, bv1.x, bv1.y, bv1.z, bv1.w};
            #pragma unroll
            for (int i = 0; i < TM; ++i)
                #pragma unroll
                for (int j = 0; j < TN; ++j)
                    acc[i][j] += a[i] * b[j];
        }
        __syncthreads();
    }

    const int cbase = n0 + tx * TN;
    #pragma unroll
    for (int i = 0; i < TM; ++i) {
        int row = m0 + ty * TM + i;
        float* orow = O + (size_t)row * HID + cbase;
        #pragma unroll
        for (int j0 = 0; j0 < TN; j0 += 4) {
            float4 bb = *(const float4*)(g_b2 + cbase + j0);
            float4 v;
            v.x = tanhf(acc[i][j0+0] + bb.x);
            v.y = tanhf(acc[i][j0+1] + bb.y);
            v.z = tanhf(acc[i][j0+2] + bb.z);
            v.w = tanhf(acc[i][j0+3] + bb.w);
            *(float4*)(orow + j0) = v;
        }
    }
}

// ---------------- output head: nodes 7 and 8 ----------------
__global__ void out_kernel(const float* __restrict__ S,
                           const float* __restrict__ out_w,
                           const float* __restrict__ out_b,
                           float* __restrict__ out)
{
    int gwarp = (blockIdx.x * blockDim.x + threadIdx.x) >> 5;
    int lane  = threadIdx.x & 31;
    if (gwarp >= B_SZ) return;
    const float* s7 = S + (size_t)gwarp * SDIM + 7 * HID;
    float v7 = 0.f, v8 = 0.f;
    #pragma unroll
    for (int h = lane; h < HID; h += 32) {
        float w = out_w[h];
        v7 += s7[h] * w;
        v8 += s7[HID + h] * w;
    }
    #pragma unroll
    for (int o = 16; o; o >>= 1) {
        v7 += __shfl_xor_sync(0xFFFFFFFFu, v7, o);
        v8 += __shfl_xor_sync(0xFFFFFFFFu, v8, o);
    }
    if (lane == 0) {
        float b = out_b[0];
        out[gwarp]        = v7 + b;   // logits_chronic  (node 7)
        out[B_SZ + gwarp] = v8 + b;   // logits_acute_and_chronic (node 8)
    }
}

// ---------------- launch ----------------
extern "C" void kernel_launch(void* const* d_in, const int* in_sizes, int n_in,
                              void* d_out, int out_size)
{
    (void)in_sizes; (void)n_in; (void)out_size;
    const float* conc   = (const float*)d_in[0];
    const float* logits = (const float*)d_in[1];
    const float* enc_w  = (const float*)d_in[2];
    const float* enc_b  = (const float*)d_in[3];
    const float* f2n_w  = (const float*)d_in[4];
    const float* f2n_b  = (const float*)d_in[5];
    const float* msg_w  = (const float*)d_in[6];
    const float* msg_b  = (const float*)d_in[7];
    const float* upd_w  = (const float*)d_in[8];
    const float* upd_b  = (const float*)d_in[9];
    const float* out_w  = (const float*)d_in[10];
    const float* out_b  = (const float*)d_in[11];
    float* out = (float*)d_out;

    float *sa = nullptr, *sb = nullptr, *sbar = nullptr;
    cudaGetSymbolAddress((void**)&sa,   g_states_a);
    cudaGetSymbolAddress((void**)&sb,   g_states_b);
    cudaGetSymbolAddress((void**)&sbar, g_sbar);

    // 1) fold msg linear into update linear
    prep_kernel<<<HID, HID>>>(msg_w, msg_b, upd_w, upd_b);

    // 2) big feature GEMM + node-encoder init -> states_a
    {
        dim3 grid(SDIM / BN, B_SZ / BM);   // (18, 128)
        gemm1_kernel<<<grid, 256>>>(conc, f2n_w, f2n_b, logits, enc_w, enc_b, sa);
    }

    // 3) 4 GNN steps (ping-pong a <-> b)
    float* cur = sa;
    float* nxt = sb;
    for (int step = 0; step < 4; ++step) {
        sbar_kernel<<<(B_SZ * 64) / 256, 256>>>(cur, sbar);
        dim3 grid(HID / BN, MROWS / BM);   // (2, 1152)
        step_gemm<<<grid, 256>>>(cur, sbar, nxt);
        float* t = cur; cur = nxt; nxt = t;
    }
    // after 4 steps, final states are in `cur` (== states_a)

    // 4) output head
    out_kernel<<<B_SZ / 8, 256>>>(cur, out_w, out_b, out);
}

// round 4
// speedup vs baseline: 2.0978x; 2.0976x over previous
#include <cuda_runtime.h>
#include <cuda_bf16.h>
#include <stdint.h>
#include <math.h>

#define B_SZ   16384
#define FDIM   2048
#define HID    256
#define NN     9
#define SDIM   (NN*HID)        // 2304
#define CATK   (2*HID)         // 512
#define MROWS  (B_SZ*NN)       // 147456

#define BM 128
#define BN 128
#define BK 32                   // bf16 K elems per chunk
#define STAGES 3
#define STG_BYTES 32768         // A 16KB + B 16KB
#define SMEM_ALLOC (STAGES*STG_BYTES + 1024)

// ---------------- device scratch (no allocation allowed) ----------------
__device__ __nv_bfloat16 g_Ah[(size_t)B_SZ*FDIM], g_Al[(size_t)B_SZ*FDIM];
__device__ __nv_bfloat16 g_Bh[(size_t)SDIM*FDIM], g_Bl[(size_t)SDIM*FDIM];
__device__ __nv_bfloat16 g_Sh0[(size_t)MROWS*HID], g_Sl0[(size_t)MROWS*HID];
__device__ __nv_bfloat16 g_Sh1[(size_t)MROWS*HID], g_Sl1[(size_t)MROWS*HID];
__device__ __nv_bfloat16 g_SBh[(size_t)MROWS*HID], g_SBl[(size_t)MROWS*HID];
__device__ __nv_bfloat16 g_Wch[HID*CATK], g_Wcl[HID*CATK];
__device__ float g_b2[HID];

// ---------------- helpers ----------------
__device__ __forceinline__ uint32_t smem_u32(const void* p){
    uint32_t a;
    asm("{ .reg .u64 t; cvta.to.shared.u64 t, %1; cvt.u32.u64 %0, t; }" : "=r"(a) : "l"(p));
    return a;
}
__device__ __forceinline__ void cpa16(uint32_t dst, const void* src){
    asm volatile("cp.async.cg.shared.global [%0], [%1], 16;" :: "r"(dst), "l"(src) : "memory");
}
__device__ __forceinline__ void cpa_commit(){ asm volatile("cp.async.commit_group;" ::: "memory"); }
__device__ __forceinline__ void cpa_wait1(){ asm volatile("cp.async.wait_group 1;" ::: "memory"); }
__device__ __forceinline__ void cpa_wait0(){ asm volatile("cp.async.wait_group 0;" ::: "memory"); }

__device__ __forceinline__ void ldm4(uint32_t addr, uint32_t* r){
    asm volatile("ldmatrix.sync.aligned.m8n8.x4.shared.b16 {%0,%1,%2,%3}, [%4];"
        : "=r"(r[0]),"=r"(r[1]),"=r"(r[2]),"=r"(r[3]) : "r"(addr));
}
__device__ __forceinline__ void mma16816(float* d, const uint32_t* a, uint32_t b0, uint32_t b1){
    asm volatile("mma.sync.aligned.m16n8k16.row.col.f32.bf16.bf16.f32 "
        "{%0,%1,%2,%3}, {%4,%5,%6,%7}, {%8,%9}, {%0,%1,%2,%3};"
        : "+f"(d[0]),"+f"(d[1]),"+f"(d[2]),"+f"(d[3])
        : "r"(a[0]),"r"(a[1]),"r"(a[2]),"r"(a[3]), "r"(b0),"r"(b1));
}

// smem tile: 128 rows x 128B; row = [hi k0..31 (64B) | lo k0..31 (64B)]
// 16B chunk c (0..7) of row r stored at r*128 + ((c ^ (r&7))<<4)  -> conflict-free ldmatrix
__device__ __forceinline__ uint32_t a_addr(uint32_t base, int row0, int c0, int hl, int lane){
    int r = row0 + (lane & 7) + ((lane >> 3) & 1) * 8;
    int c = hl*4 + c0 + (lane >> 4);
    return base + r*128 + ((c ^ (r & 7)) << 4);
}
__device__ __forceinline__ uint32_t b_addr(uint32_t base, int n0, int c0, int hl, int lane){
    int r = n0 + (lane & 7) + (lane >> 4) * 8;
    int c = hl*4 + c0 + ((lane >> 3) & 1);
    return base + r*128 + ((c ^ (r & 7)) << 4);
}

__device__ __forceinline__ void split2(float v, __nv_bfloat16& h, __nv_bfloat16& l){
    h = __float2bfloat16(v);
    l = __float2bfloat16(v - __bfloat162float(h));
}
__device__ __forceinline__ uint32_t pk2(__nv_bfloat16 a, __nv_bfloat16 b){
    return (uint32_t)__bfloat16_as_ushort(a) | ((uint32_t)__bfloat16_as_ushort(b)<<16);
}
__device__ __forceinline__ float bflo(uint32_t w){
    return __bfloat162float(__ushort_as_bfloat16((unsigned short)(w & 0xFFFFu)));
}
__device__ __forceinline__ float bfhi(uint32_t w){
    return __bfloat162float(__ushort_as_bfloat16((unsigned short)(w >> 16)));
}
__device__ __forceinline__ float tanh_fast(float x){
    float ax = fabsf(x);
    float z = __expf(-2.f*ax);
    float y = __fdividef(1.f - z, 1.f + z);
    return copysignf(y, x);
}

// load one stage: A 128x32 (hi+lo) + B 128x32 (hi+lo)
__device__ __forceinline__ void load_stage(uint32_t base, int tid,
    const __nv_bfloat16* aH, const __nv_bfloat16* aL, int lda,
    const __nv_bfloat16* bH, const __nv_bfloat16* bL, int ldb)
{
    #pragma unroll
    for (int i=0;i<4;i++){
        int id = i*256 + tid;
        int row = id>>3, c = id&7;
        const __nv_bfloat16* src = (c<4 ? aH : aL) + (size_t)row*lda + ((c&3)<<3);
        cpa16(base + row*128 + ((c ^ (row&7))<<4), src);
    }
    #pragma unroll
    for (int i=0;i<4;i++){
        int id = i*256 + tid;
        int row = id>>3, c = id&7;
        const __nv_bfloat16* src = (c<4 ? bH : bL) + (size_t)row*ldb + ((c&3)<<3);
        cpa16(base + 16384 + row*128 + ((c ^ (row&7))<<4), src);
    }
    cpa_commit();
}

// compute one 32-K chunk: 3 products AhBh + AhBl + AlBh
__device__ __forceinline__ void compute_stage(uint32_t bA, float acc[2][8][4],
                                              int warp_m, int warp_n, int lane)
{
    uint32_t bB = bA + 16384;
    #pragma unroll
    for (int k16=0; k16<2; k16++){
        int c0 = k16*2;
        uint32_t aH[2][4], aL[2][4], bH[4][4], bL[4][4];
        #pragma unroll
        for (int mt=0; mt<2; mt++){
            ldm4(a_addr(bA, warp_m + mt*16, c0, 0, lane), aH[mt]);
            ldm4(a_addr(bA, warp_m + mt*16, c0, 1, lane), aL[mt]);
        }
        #pragma unroll
        for (int g=0; g<4; g++){
            ldm4(b_addr(bB, warp_n + g*16, c0, 0, lane), bH[g]);
            ldm4(b_addr(bB, warp_n + g*16, c0, 1, lane), bL[g]);
        }
        #pragma unroll
        for (int mt=0; mt<2; mt++)
            #pragma unroll
            for (int nt=0; nt<8; nt++){
                int g = nt>>1, p = (nt&1)*2;
                mma16816(acc[mt][nt], aH[mt], bH[g][p], bH[g][p+1]);
                mma16816(acc[mt][nt], aH[mt], bL[g][p], bL[g][p+1]);
                mma16816(acc[mt][nt], aL[mt], bH[g][p], bH[g][p+1]);
            }
    }
}

// ---------------- split fp32 -> bf16 hi/lo ----------------
__global__ void split_kernel(const float* __restrict__ x,
                             __nv_bfloat16* __restrict__ h,
                             __nv_bfloat16* __restrict__ l, int n4)
{
    int i = blockIdx.x*blockDim.x + threadIdx.x;
    if (i >= n4) return;
    float4 v = ((const float4*)x)[i];
    __nv_bfloat16 h0,l0,h1,l1,h2,l2,h3,l3;
    split2(v.x,h0,l0); split2(v.y,h1,l1); split2(v.z,h2,l2); split2(v.w,h3,l3);
    ((uint2*)h)[i] = make_uint2(pk2(h0,h1), pk2(h2,h3));
    ((uint2*)l)[i] = make_uint2(pk2(l0,l1), pk2(l2,l3));
}

// ---------------- prep: fold msg linear into update linear; split ----------------
__global__ void prep_kernel(const float* __restrict__ msg_w, const float* __restrict__ msg_b,
                            const float* __restrict__ upd_w, const float* __restrict__ upd_b)
{
    int o = blockIdx.x, k = threadIdx.x;
    const float* u2 = upd_w + o*CATK + HID;
    __nv_bfloat16 hh, ll;
    split2(upd_w[o*CATK + k], hh, ll);
    g_Wch[o*CATK + k] = hh; g_Wcl[o*CATK + k] = ll;
    float acc = 0.f;
    #pragma unroll 4
    for (int m=0;m<HID;m++) acc += u2[m]*msg_w[m*HID + k];
    split2(acc, hh, ll);
    g_Wch[o*CATK + HID + k] = hh; g_Wcl[o*CATK + HID + k] = ll;
    if (k==0){
        float bb = upd_b[o];
        for (int m=0;m<HID;m++) bb += u2[m]*msg_b[m];
        g_b2[o] = bb;
    }
}

// ---------------- GEMM1: conc @ f2n_w^T + biases + encoder -> Sh0/Sl0 ----------------
__global__ void __launch_bounds__(256,1) gemm1_mma(
    const float* __restrict__ f2n_b, const float* __restrict__ logits,
    const float* __restrict__ enc_w, const float* __restrict__ enc_b,
    __nv_bfloat16* __restrict__ Sh, __nv_bfloat16* __restrict__ Sl)
{
    extern __shared__ char smraw[];
    uint32_t sb = (smem_u32(smraw) + 1023u) & ~1023u;
    const int tid = threadIdx.x, wid = tid>>5, lane = tid&31;
    const int n0 = blockIdx.x * BN;
    const int m0 = blockIdx.y * BM;
    const int node = blockIdx.x >> 1;
    const int warp_m = (wid & 3) * 32;
    const int warp_n = (wid >> 2) * 64;

    const __nv_bfloat16* Ah = g_Ah + (size_t)m0*FDIM;
    const __nv_bfloat16* Al = g_Al + (size_t)m0*FDIM;
    const __nv_bfloat16* Bh = g_Bh + (size_t)n0*FDIM;
    const __nv_bfloat16* Bl = g_Bl + (size_t)n0*FDIM;

    float acc[2][8][4];
    #pragma unroll
    for (int a=0;a<2;a++) for (int b=0;b<8;b++) for (int c=0;c<4;c++) acc[a][b][c]=0.f;

    load_stage(sb,             tid, Ah,    Al,    FDIM, Bh,    Bl,    FDIM);
    load_stage(sb+STG_BYTES,   tid, Ah+BK, Al+BK, FDIM, Bh+BK, Bl+BK, FDIM);

    const int NC = FDIM/BK;   // 64
    #pragma unroll 1
    for (int c=0;c<NC;c++){
        if (c == NC-1) cpa_wait0(); else cpa_wait1();
        __syncthreads();
        if (c+2 < NC){
            int s2 = (c+2)%STAGES;
            int kc = (c+2)*BK;
            load_stage(sb + s2*STG_BYTES, tid, Ah+kc, Al+kc, FDIM, Bh+kc, Bl+kc, FDIM);
        }
        compute_stage(sb + (c%STAGES)*STG_BYTES, acc, warp_m, warp_n, lane);
    }

    // epilogue
    const int lane4 = lane>>2, lane2 = (lane&3)*2;
    #pragma unroll
    for (int mt=0; mt<2; mt++){
        int r0 = m0 + warp_m + mt*16 + lane4;
        float lg0 = logits[(size_t)r0*NN + node];
        float lg1 = logits[(size_t)(r0+8)*NN + node];
        #pragma unroll
        for (int nt=0; nt<8; nt++){
            int cg = n0 + warp_n + nt*8 + lane2;
            int h  = cg & 255;
            float fb0 = f2n_b[cg] + enc_b[h],   fb1 = f2n_b[cg+1] + enc_b[h+1];
            float ew0 = enc_w[h],               ew1 = enc_w[h+1];
            float* a4 = acc[mt][nt];
            float v00 = a4[0] + fb0 + lg0*ew0;
            float v01 = a4[1] + fb1 + lg0*ew1;
            float v10 = a4[2] + fb0 + lg1*ew0;
            float v11 = a4[3] + fb1 + lg1*ew1;
            __nv_bfloat16 h00,l00,h01,l01,h10,l10,h11,l11;
            split2(v00,h00,l00); split2(v01,h01,l01);
            split2(v10,h10,l10); split2(v11,h11,l11);
            size_t o0 = (size_t)r0*SDIM + cg;
            size_t o1 = (size_t)(r0+8)*SDIM + cg;
            *(uint32_t*)(Sh + o0) = pk2(h00,h01);
            *(uint32_t*)(Sl + o0) = pk2(l00,l01);
            *(uint32_t*)(Sh + o1) = pk2(h10,h11);
            *(uint32_t*)(Sl + o1) = pk2(l10,l11);
        }
    }
}

// ---------------- step GEMM: tanh([S|SB] @ Wc^T + b2) -> Oh/Ol ----------------
__global__ void __launch_bounds__(256,1) step_mma(
    const __nv_bfloat16* __restrict__ Sh, const __nv_bfloat16* __restrict__ Sl,
    const __nv_bfloat16* __restrict__ SBh, const __nv_bfloat16* __restrict__ SBl,
    __nv_bfloat16* __restrict__ Oh, __nv_bfloat16* __restrict__ Ol)
{
    extern __shared__ char smraw[];
    uint32_t sb = (smem_u32(smraw) + 1023u) & ~1023u;
    const int tid = threadIdx.x, wid = tid>>5, lane = tid&31;
    const int n0 = blockIdx.x * BN;   // 0 or 128
    const int m0 = blockIdx.y * BM;
    const int warp_m = (wid & 3) * 32;
    const int warp_n = (wid >> 2) * 64;

    float acc[2][8][4];
    #pragma unroll
    for (int a=0;a<2;a++) for (int b=0;b<8;b++) for (int c=0;c<4;c++) acc[a][b][c]=0.f;

    const __nv_bfloat16* aSrcH[2] = { Sh + (size_t)m0*HID, SBh + (size_t)m0*HID };
    const __nv_bfloat16* aSrcL[2] = { Sl + (size_t)m0*HID, SBl + (size_t)m0*HID };
    const __nv_bfloat16* Wh = g_Wch + (size_t)n0*CATK;
    const __nv_bfloat16* Wl = g_Wcl + (size_t)n0*CATK;

    const int NC = CATK/BK;   // 16
    {
        load_stage(sb,           tid, aSrcH[0],    aSrcL[0],    HID, Wh,    Wl,    CATK);
        load_stage(sb+STG_BYTES, tid, aSrcH[0]+BK, aSrcL[0]+BK, HID, Wh+BK, Wl+BK, CATK);
    }
    #pragma unroll 1
    for (int c=0;c<NC;c++){
        if (c == NC-1) cpa_wait0(); else cpa_wait1();
        __syncthreads();
        if (c+2 < NC){
            int s2 = (c+2)%STAGES;
            int kg = (c+2)*BK;              // 0..480
            int half = kg >> 8;             // 0: S, 1: SB
            int kl = kg & 255;
            load_stage(sb + s2*STG_BYTES, tid,
                       aSrcH[half]+kl, aSrcL[half]+kl, HID, Wh+kg, Wl+kg, CATK);
        }
        compute_stage(sb + (c%STAGES)*STG_BYTES, acc, warp_m, warp_n, lane);
    }

    const int lane4 = lane>>2, lane2 = (lane&3)*2;
    #pragma unroll
    for (int mt=0; mt<2; mt++){
        int r0 = m0 + warp_m + mt*16 + lane4;
        #pragma unroll
        for (int nt=0; nt<8; nt++){
            int cg = n0 + warp_n + nt*8 + lane2;
            float b0 = g_b2[cg], b1 = g_b2[cg+1];
            float* a4 = acc[mt][nt];
            float v00 = tanh_fast(a4[0] + b0);
            float v01 = tanh_fast(a4[1] + b1);
            float v10 = tanh_fast(a4[2] + b0);
            float v11 = tanh_fast(a4[3] + b1);
            __nv_bfloat16 h00,l00,h01,l01,h10,l10,h11,l11;
            split2(v00,h00,l00); split2(v01,h01,l01);
            split2(v10,h10,l10); split2(v11,h11,l11);
            size_t o0 = (size_t)r0*HID + cg;
            size_t o1 = (size_t)(r0+8)*HID + cg;
            *(uint32_t*)(Oh + o0) = pk2(h00,h01);
            *(uint32_t*)(Ol + o0) = pk2(l00,l01);
            *(uint32_t*)(Oh + o1) = pk2(h10,h11);
            *(uint32_t*)(Ol + o1) = pk2(l10,l11);
        }
    }
}

// ---------------- adjacency aggregate ----------------
__global__ void sbar_kernel(const __nv_bfloat16* __restrict__ Sh, const __nv_bfloat16* __restrict__ Sl,
                            __nv_bfloat16* __restrict__ Oh, __nv_bfloat16* __restrict__ Ol)
{
    int idx = blockIdx.x*blockDim.x + threadIdx.x;
    if (idx >= B_SZ*64) return;
    int b = idx>>6, c4 = (idx&63)<<2;
    size_t base = (size_t)b*SDIM + c4;
    float s[9][4];
    #pragma unroll
    for (int n=0;n<9;n++){
        uint2 vh = *(const uint2*)(Sh + base + n*HID);
        uint2 vl = *(const uint2*)(Sl + base + n*HID);
        s[n][0] = bflo(vh.x)+bflo(vl.x);
        s[n][1] = bfhi(vh.x)+bfhi(vl.x);
        s[n][2] = bflo(vh.y)+bflo(vl.y);
        s[n][3] = bfhi(vh.y)+bfhi(vl.y);
    }
    float o[9][4];
    #pragma unroll
    for (int e=0;e<4;e++){
        float tot = 0.f;
        #pragma unroll
        for (int n=0;n<9;n++) tot += s[n][e];
        float hub = s[0][e] + s[7][e] + s[8][e];
        float m78 = (tot - s[1][e]) * 0.125f;
        o[0][e] = tot * (1.f/9.f);
        o[1][e] = (s[0][e] + s[1][e]) * 0.5f;
        #pragma unroll
        for (int n=2;n<=6;n++) o[n][e] = (hub + s[n][e]) * 0.25f;
        o[7][e] = m78; o[8][e] = m78;
    }
    #pragma unroll
    for (int n=0;n<9;n++){
        __nv_bfloat16 h0,l0,h1,l1,h2,l2,h3,l3;
        split2(o[n][0],h0,l0); split2(o[n][1],h1,l1);
        split2(o[n][2],h2,l2); split2(o[n][3],h3,l3);
        *(uint2*)(Oh + base + n*HID) = make_uint2(pk2(h0,h1), pk2(h2,h3));
        *(uint2*)(Ol + base + n*HID) = make_uint2(pk2(l0,l1), pk2(l2,l3));
    }
}

// ---------------- output head (nodes 7, 8) ----------------
__global__ void out_kernel(const __nv_bfloat16* __restrict__ Sh, const __nv_bfloat16* __restrict__ Sl,
                           const float* __restrict__ out_w, const float* __restrict__ out_b,
                           float* __restrict__ out)
{
    int gwarp = (blockIdx.x*blockDim.x + threadIdx.x) >> 5;
    int lane  = threadIdx.x & 31;
    if (gwarp >= B_SZ) return;
    size_t b7 = ((size_t)gwarp*NN + 7)*HID;
    float v7 = 0.f, v8 = 0.f;
    #pragma unroll
    for (int h = lane; h < HID; h += 32){
        float w = out_w[h];
        v7 += (__bfloat162float(Sh[b7+h])     + __bfloat162float(Sl[b7+h]))     * w;
        v8 += (__bfloat162float(Sh[b7+HID+h]) + __bfloat162float(Sl[b7+HID+h])) * w;
    }
    #pragma unroll
    for (int o = 16; o; o >>= 1){
        v7 += __shfl_xor_sync(0xFFFFFFFFu, v7, o);
        v8 += __shfl_xor_sync(0xFFFFFFFFu, v8, o);
    }
    if (lane == 0){
        float b = out_b[0];
        out[gwarp]        = v7 + b;
        out[B_SZ + gwarp] = v8 + b;
    }
}

// ---------------- launch ----------------
extern "C" void kernel_launch(void* const* d_in, const int* in_sizes, int n_in,
                              void* d_out, int out_size)
{
    (void)in_sizes; (void)n_in; (void)out_size;
    const float* conc   = (const float*)d_in[0];
    const float* logits = (const float*)d_in[1];
    const float* enc_w  = (const float*)d_in[2];
    const float* enc_b  = (const float*)d_in[3];
    const float* f2n_w  = (const float*)d_in[4];
    const float* f2n_b  = (const float*)d_in[5];
    const float* msg_w  = (const float*)d_in[6];
    const float* msg_b  = (const float*)d_in[7];
    const float* upd_w  = (const float*)d_in[8];
    const float* upd_b  = (const float*)d_in[9];
    const float* out_w  = (const float*)d_in[10];
    const float* out_b  = (const float*)d_in[11];
    float* out = (float*)d_out;

    __nv_bfloat16 *ah,*al,*bh,*bl,*sh0,*sl0,*sh1,*sl1,*sbh,*sbl;
    cudaGetSymbolAddress((void**)&ah,  g_Ah);  cudaGetSymbolAddress((void**)&al,  g_Al);
    cudaGetSymbolAddress((void**)&bh,  g_Bh);  cudaGetSymbolAddress((void**)&bl,  g_Bl);
    cudaGetSymbolAddress((void**)&sh0, g_Sh0); cudaGetSymbolAddress((void**)&sl0, g_Sl0);
    cudaGetSymbolAddress((void**)&sh1, g_Sh1); cudaGetSymbolAddress((void**)&sl1, g_Sl1);
    cudaGetSymbolAddress((void**)&sbh, g_SBh); cudaGetSymbolAddress((void**)&sbl, g_SBl);

    static int smem_set = 0;
    if (!smem_set){
        cudaFuncSetAttribute(gemm1_mma, cudaFuncAttributeMaxDynamicSharedMemorySize, SMEM_ALLOC);
        cudaFuncSetAttribute(step_mma,  cudaFuncAttributeMaxDynamicSharedMemorySize, SMEM_ALLOC);
        smem_set = 1;
    }

    // 0) splits + prep
    split_kernel<<<(B_SZ*FDIM/4)/256, 256>>>(conc,  ah, al, B_SZ*FDIM/4);
    split_kernel<<<(SDIM*FDIM/4)/256, 256>>>(f2n_w, bh, bl, SDIM*FDIM/4);
    prep_kernel<<<HID, HID>>>(msg_w, msg_b, upd_w, upd_b);

    // 1) big feature GEMM -> Sh0/Sl0
    {
        dim3 grid(SDIM/BN, B_SZ/BM);   // (18, 128)
        gemm1_mma<<<grid, 256, SMEM_ALLOC>>>(f2n_b, logits, enc_w, enc_b, sh0, sl0);
    }

    // 2) 4 GNN steps (ping-pong)
    __nv_bfloat16 *ch = sh0, *cl = sl0, *nh = sh1, *nl = sl1;
    for (int step = 0; step < 4; ++step){
        sbar_kernel<<<(B_SZ*64)/256, 256>>>(ch, cl, sbh, sbl);
        dim3 grid(HID/BN, MROWS/BM);   // (2, 1152)
        step_mma<<<grid, 256, SMEM_ALLOC>>>(ch, cl, sbh, sbl, nh, nl);
        __nv_bfloat16* t;
        t = ch; ch = nh; nh = t;
        t = cl; cl = nl; nl = t;
    }

    // 3) output head
    out_kernel<<<B_SZ/8, 256>>>(ch, cl, out_w, out_b, out);
}

// round 5
// speedup vs baseline: 3.6325x; 1.7316x over previous
#include <cuda_runtime.h>
#include <cuda_fp16.h>
#include <stdint.h>
#include <math.h>

#define B_SZ   16384
#define FDIM   2048
#define HID    256
#define NN     9
#define SDIM   (NN*HID)        // 2304
#define CATK   (2*HID)         // 512
#define MROWS  (B_SZ*NN)       // 147456

#define BM 128
#define BN 128
#define BK 64                   // fp16 K elems per chunk
#define STAGES 3
#define STG_BYTES (48*1024)     // A 16KB + Bh 16KB + Bl 16KB
#define OFF_BH 16384
#define OFF_BL 32768
#define SMEM_ALLOC (STAGES*STG_BYTES + 1024)

// ---------------- device scratch (no allocation allowed) ----------------
__device__ __half g_A16[(size_t)B_SZ*FDIM];                    // 64MB  (conc fp16)
__device__ __half g_Bh[(size_t)SDIM*FDIM], g_Bl[(size_t)SDIM*FDIM];  // 9MB each
__device__ __half g_S0[(size_t)MROWS*HID];                     // 75MB  states ping
__device__ __half g_S1[(size_t)MROWS*HID];                     // 75MB  states pong
__device__ __half g_SB[(size_t)MROWS*HID];                     // 75MB  aggregated
__device__ __half g_Wh[HID*CATK], g_Wl[HID*CATK];
__device__ float g_b2[HID];

// ---------------- helpers ----------------
__device__ __forceinline__ uint32_t smem_u32(const void* p){
    uint32_t a;
    asm("{ .reg .u64 t; cvta.to.shared.u64 t, %1; cvt.u32.u64 %0, t; }" : "=r"(a) : "l"(p));
    return a;
}
__device__ __forceinline__ void cpa16(uint32_t dst, const void* src){
    asm volatile("cp.async.cg.shared.global [%0], [%1], 16;" :: "r"(dst), "l"(src) : "memory");
}
__device__ __forceinline__ void cpa_commit(){ asm volatile("cp.async.commit_group;" ::: "memory"); }
__device__ __forceinline__ void cpa_wait1(){ asm volatile("cp.async.wait_group 1;" ::: "memory"); }
__device__ __forceinline__ void cpa_wait0(){ asm volatile("cp.async.wait_group 0;" ::: "memory"); }

__device__ __forceinline__ void ldm4(uint32_t addr, uint32_t* r){
    asm volatile("ldmatrix.sync.aligned.m8n8.x4.shared.b16 {%0,%1,%2,%3}, [%4];"
        : "=r"(r[0]),"=r"(r[1]),"=r"(r[2]),"=r"(r[3]) : "r"(addr));
}
__device__ __forceinline__ void mma16816(float* d, const uint32_t* a, uint32_t b0, uint32_t b1){
    asm volatile("mma.sync.aligned.m16n8k16.row.col.f32.f16.f16.f32 "
        "{%0,%1,%2,%3}, {%4,%5,%6,%7}, {%8,%9}, {%0,%1,%2,%3};"
        : "+f"(d[0]),"+f"(d[1]),"+f"(d[2]),"+f"(d[3])
        : "r"(a[0]),"r"(a[1]),"r"(a[2]),"r"(a[3]), "r"(b0),"r"(b1));
}

// smem tile: rows of 128B (64 fp16), chunk c (0..7, 16B) at r*128 + ((c^(r&7))<<4)
__device__ __forceinline__ uint32_t a_addr(uint32_t base, int row0, int c0, int lane){
    int r = row0 + (lane & 7) + ((lane >> 3) & 1) * 8;
    int c = c0 + (lane >> 4);
    return base + r*128 + ((c ^ (r & 7)) << 4);
}
__device__ __forceinline__ uint32_t b_addr(uint32_t base, int n0, int c0, int lane){
    int r = n0 + (lane & 7) + (lane >> 4) * 8;
    int c = c0 + ((lane >> 3) & 1);
    return base + r*128 + ((c ^ (r & 7)) << 4);
}

__device__ __forceinline__ uint32_t pkh2(float a, float b){
    __half2 h = __floats2half2_rn(a, b);
    return *(uint32_t*)&h;
}
__device__ __forceinline__ float tanh_fast(float x){
    float ax = fabsf(x);
    float z = __expf(-2.f*ax);
    float y = __fdividef(1.f - z, 1.f + z);
    return copysignf(y, x);
}

// load one stage: A 128x64 fp16 + Bh 128x64 + Bl 128x64
__device__ __forceinline__ void load_stage(uint32_t base, int tid,
    const __half* aP, int lda, const __half* bhP, const __half* blP, int ldb)
{
    #pragma unroll
    for (int i=0;i<4;i++){
        int id = i*256 + tid;
        int row = id>>3, c = id&7;
        uint32_t d = row*128 + ((c ^ (row&7))<<4);
        cpa16(base + d, aP + (size_t)row*lda + (c<<3));
    }
    #pragma unroll
    for (int i=0;i<4;i++){
        int id = i*256 + tid;
        int row = id>>3, c = id&7;
        uint32_t d = row*128 + ((c ^ (row&7))<<4);
        cpa16(base + OFF_BH + d, bhP + (size_t)row*ldb + (c<<3));
        cpa16(base + OFF_BL + d, blP + (size_t)row*ldb + (c<<3));
    }
    cpa_commit();
}

// one 64-K chunk: 2 products A*(Bh) + A*(Bl); warp tile 64(M) x 32(N)
__device__ __forceinline__ void compute_stage(uint32_t base, float acc[4][4][4],
                                              int warp_m, int warp_n, int lane)
{
    #pragma unroll
    for (int k16=0; k16<4; k16++){
        int c0 = 2*k16;
        uint32_t aF[4][4], bH[2][4], bL[2][4];
        #pragma unroll
        for (int mt=0; mt<4; mt++)
            ldm4(a_addr(base, warp_m + mt*16, c0, lane), aF[mt]);
        #pragma unroll
        for (int g=0; g<2; g++){
            ldm4(b_addr(base + OFF_BH, warp_n + g*16, c0, lane), bH[g]);
            ldm4(b_addr(base + OFF_BL, warp_n + g*16, c0, lane), bL[g]);
        }
        #pragma unroll
        for (int mt=0; mt<4; mt++)
            #pragma unroll
            for (int nt=0; nt<4; nt++){
                int g = nt>>1, p = (nt&1)*2;
                mma16816(acc[mt][nt], aF[mt], bH[g][p], bH[g][p+1]);
                mma16816(acc[mt][nt], aF[mt], bL[g][p], bL[g][p+1]);
            }
    }
}

// ---------------- converts ----------------
__global__ void conv16_kernel(const float* __restrict__ x, __half* __restrict__ h, int n4)
{
    int i = blockIdx.x*blockDim.x + threadIdx.x;
    if (i >= n4) return;
    float4 v = ((const float4*)x)[i];
    ((uint2*)h)[i] = make_uint2(pkh2(v.x,v.y), pkh2(v.z,v.w));
}
__global__ void split16_kernel(const float* __restrict__ x,
                               __half* __restrict__ h, __half* __restrict__ l, int n4)
{
    int i = blockIdx.x*blockDim.x + threadIdx.x;
    if (i >= n4) return;
    float4 v = ((const float4*)x)[i];
    float h0 = __half2float(__float2half_rn(v.x));
    float h1 = __half2float(__float2half_rn(v.y));
    float h2 = __half2float(__float2half_rn(v.z));
    float h3 = __half2float(__float2half_rn(v.w));
    ((uint2*)h)[i] = make_uint2(pkh2(h0,h1), pkh2(h2,h3));
    ((uint2*)l)[i] = make_uint2(pkh2(v.x-h0, v.y-h1), pkh2(v.z-h2, v.w-h3));
}

// ---------------- prep: fold msg linear into update linear; split fp16 ----------------
__global__ void prep_kernel(const float* __restrict__ msg_w, const float* __restrict__ msg_b,
                            const float* __restrict__ upd_w, const float* __restrict__ upd_b)
{
    int o = blockIdx.x, k = threadIdx.x;
    const float* u2 = upd_w + o*CATK + HID;
    float w1 = upd_w[o*CATK + k];
    float h1 = __half2float(__float2half_rn(w1));
    g_Wh[o*CATK + k] = __float2half_rn(w1);
    g_Wl[o*CATK + k] = __float2half_rn(w1 - h1);
    float acc = 0.f;
    #pragma unroll 4
    for (int m=0;m<HID;m++) acc += u2[m]*msg_w[m*HID + k];
    float h2 = __half2float(__float2half_rn(acc));
    g_Wh[o*CATK + HID + k] = __float2half_rn(acc);
    g_Wl[o*CATK + HID + k] = __float2half_rn(acc - h2);
    if (k==0){
        float bb = upd_b[o];
        for (int m=0;m<HID;m++) bb += u2[m]*msg_b[m];
        g_b2[o] = bb;
    }
}

// ---------------- GEMM1: conc @ f2n_w^T + biases + encoder -> S0 ----------------
__global__ void __launch_bounds__(256,1) gemm1_mma(
    const float* __restrict__ f2n_b, const float* __restrict__ logits,
    const float* __restrict__ enc_w, const float* __restrict__ enc_b,
    __half* __restrict__ S)
{
    extern __shared__ char smraw[];
    uint32_t sb = (smem_u32(smraw) + 1023u) & ~1023u;
    const int tid = threadIdx.x, wid = tid>>5, lane = tid&31;
    const int n0 = blockIdx.x * BN;
    const int m0 = blockIdx.y * BM;
    const int node = blockIdx.x >> 1;
    const int warp_m = (wid & 1) * 64;
    const int warp_n = (wid >> 1) * 32;

    const __half* A  = g_A16 + (size_t)m0*FDIM;
    const __half* Bh = g_Bh  + (size_t)n0*FDIM;
    const __half* Bl = g_Bl  + (size_t)n0*FDIM;

    float acc[4][4][4];
    #pragma unroll
    for (int a=0;a<4;a++) for (int b=0;b<4;b++) for (int c=0;c<4;c++) acc[a][b][c]=0.f;

    load_stage(sb,             tid, A,    FDIM, Bh,    Bl,    FDIM);
    load_stage(sb+STG_BYTES,   tid, A+BK, FDIM, Bh+BK, Bl+BK, FDIM);

    const int NC = FDIM/BK;   // 32
    #pragma unroll 1
    for (int c=0;c<NC;c++){
        if (c == NC-1) cpa_wait0(); else cpa_wait1();
        __syncthreads();
        if (c+2 < NC){
            int s2 = (c+2)%STAGES;
            int kc = (c+2)*BK;
            load_stage(sb + s2*STG_BYTES, tid, A+kc, FDIM, Bh+kc, Bl+kc, FDIM);
        }
        compute_stage(sb + (c%STAGES)*STG_BYTES, acc, warp_m, warp_n, lane);
    }

    const int lane4 = lane>>2, lane2 = (lane&3)*2;
    #pragma unroll
    for (int mt=0; mt<4; mt++){
        int r0 = m0 + warp_m + mt*16 + lane4;
        float lg0 = logits[(size_t)r0*NN + node];
        float lg1 = logits[(size_t)(r0+8)*NN + node];
        #pragma unroll
        for (int nt=0; nt<4; nt++){
            int cg = n0 + warp_n + nt*8 + lane2;
            int h  = cg & 255;
            float fb0 = f2n_b[cg] + enc_b[h],   fb1 = f2n_b[cg+1] + enc_b[h+1];
            float ew0 = enc_w[h],               ew1 = enc_w[h+1];
            float* a4 = acc[mt][nt];
            *(uint32_t*)(S + (size_t)r0*SDIM + cg)     = pkh2(a4[0]+fb0+lg0*ew0, a4[1]+fb1+lg0*ew1);
            *(uint32_t*)(S + (size_t)(r0+8)*SDIM + cg) = pkh2(a4[2]+fb0+lg1*ew0, a4[3]+fb1+lg1*ew1);
        }
    }
}

// ---------------- step GEMM: tanh([S|SB] @ Wc^T + b2) -> O ----------------
__global__ void __launch_bounds__(256,1) step_mma(
    const __half* __restrict__ S, const __half* __restrict__ SB,
    __half* __restrict__ O)
{
    extern __shared__ char smraw[];
    uint32_t sb = (smem_u32(smraw) + 1023u) & ~1023u;
    const int tid = threadIdx.x, wid = tid>>5, lane = tid&31;
    const int n0 = blockIdx.x * BN;   // 0 or 128
    const int m0 = blockIdx.y * BM;
    const int warp_m = (wid & 1) * 64;
    const int warp_n = (wid >> 1) * 32;

    float acc[4][4][4];
    #pragma unroll
    for (int a=0;a<4;a++) for (int b=0;b<4;b++) for (int c=0;c<4;c++) acc[a][b][c]=0.f;

    const __half* aS  = S  + (size_t)m0*HID;
    const __half* aSB = SB + (size_t)m0*HID;
    const __half* Wh = g_Wh + (size_t)n0*CATK;
    const __half* Wl = g_Wl + (size_t)n0*CATK;

    load_stage(sb,           tid, aS,    HID, Wh,    Wl,    CATK);
    load_stage(sb+STG_BYTES, tid, aS+BK, HID, Wh+BK, Wl+BK, CATK);

    const int NC = CATK/BK;   // 8
    #pragma unroll 1
    for (int c=0;c<NC;c++){
        if (c == NC-1) cpa_wait0(); else cpa_wait1();
        __syncthreads();
        if (c+2 < NC){
            int s2 = (c+2)%STAGES;
            int kg = (c+2)*BK;
            const __half* aP = (kg < HID ? aS : aSB) + (kg & (HID-1));
            load_stage(sb + s2*STG_BYTES, tid, aP, HID, Wh+kg, Wl+kg, CATK);
        }
        compute_stage(sb + (c%STAGES)*STG_BYTES, acc, warp_m, warp_n, lane);
    }

    const int lane4 = lane>>2, lane2 = (lane&3)*2;
    #pragma unroll
    for (int mt=0; mt<4; mt++){
        int r0 = m0 + warp_m + mt*16 + lane4;
        #pragma unroll
        for (int nt=0; nt<4; nt++){
            int cg = n0 + warp_n + nt*8 + lane2;
            float b0 = g_b2[cg], b1 = g_b2[cg+1];
            float* a4 = acc[mt][nt];
            *(uint32_t*)(O + (size_t)r0*HID + cg)     = pkh2(tanh_fast(a4[0]+b0), tanh_fast(a4[1]+b1));
            *(uint32_t*)(O + (size_t)(r0+8)*HID + cg) = pkh2(tanh_fast(a4[2]+b0), tanh_fast(a4[3]+b1));
        }
    }
}

// ---------------- adjacency aggregate (fp16 -> fp16) ----------------
__global__ void sbar_kernel(const __half* __restrict__ S, __half* __restrict__ SB)
{
    int idx = blockIdx.x*blockDim.x + threadIdx.x;
    if (idx >= B_SZ*64) return;
    int b = idx>>6, c4 = (idx&63)<<2;
    size_t base = (size_t)b*SDIM + c4;
    float s[9][4];
    #pragma unroll
    for (int n=0;n<9;n++){
        uint2 v = *(const uint2*)(S + base + n*HID);
        float2 f01 = __half22float2(*(__half2*)&v.x);
        float2 f23 = __half22float2(*(__half2*)&v.y);
        s[n][0]=f01.x; s[n][1]=f01.y; s[n][2]=f23.x; s[n][3]=f23.y;
    }
    float o[9][4];
    #pragma unroll
    for (int e=0;e<4;e++){
        float tot = 0.f;
        #pragma unroll
        for (int n=0;n<9;n++) tot += s[n][e];
        float hub = s[0][e] + s[7][e] + s[8][e];
        float m78 = (tot - s[1][e]) * 0.125f;
        o[0][e] = tot * (1.f/9.f);
        o[1][e] = (s[0][e] + s[1][e]) * 0.5f;
        #pragma unroll
        for (int n=2;n<=6;n++) o[n][e] = (hub + s[n][e]) * 0.25f;
        o[7][e] = m78; o[8][e] = m78;
    }
    #pragma unroll
    for (int n=0;n<9;n++)
        *(uint2*)(SB + base + n*HID) = make_uint2(pkh2(o[n][0],o[n][1]), pkh2(o[n][2],o[n][3]));
}

// ---------------- output head (nodes 7, 8) ----------------
__global__ void out_kernel(const __half* __restrict__ S,
                           const float* __restrict__ out_w, const float* __restrict__ out_b,
                           float* __restrict__ out)
{
    int gwarp = (blockIdx.x*blockDim.x + threadIdx.x) >> 5;
    int lane  = threadIdx.x & 31;
    if (gwarp >= B_SZ) return;
    size_t b7 = ((size_t)gwarp*NN + 7)*HID;
    float v7 = 0.f, v8 = 0.f;
    #pragma unroll
    for (int h = lane; h < HID; h += 32){
        float w = out_w[h];
        v7 += __half2float(S[b7+h])     * w;
        v8 += __half2float(S[b7+HID+h]) * w;
    }
    #pragma unroll
    for (int o = 16; o; o >>= 1){
        v7 += __shfl_xor_sync(0xFFFFFFFFu, v7, o);
        v8 += __shfl_xor_sync(0xFFFFFFFFu, v8, o);
    }
    if (lane == 0){
        float b = out_b[0];
        out[gwarp]        = v7 + b;
        out[B_SZ + gwarp] = v8 + b;
    }
}

// ---------------- launch ----------------
extern "C" void kernel_launch(void* const* d_in, const int* in_sizes, int n_in,
                              void* d_out, int out_size)
{
    (void)in_sizes; (void)n_in; (void)out_size;
    const float* conc   = (const float*)d_in[0];
    const float* logits = (const float*)d_in[1];
    const float* enc_w  = (const float*)d_in[2];
    const float* enc_b  = (const float*)d_in[3];
    const float* f2n_w  = (const float*)d_in[4];
    const float* f2n_b  = (const float*)d_in[5];
    const float* msg_w  = (const float*)d_in[6];
    const float* msg_b  = (const float*)d_in[7];
    const float* upd_w  = (const float*)d_in[8];
    const float* upd_b  = (const float*)d_in[9];
    const float* out_w  = (const float*)d_in[10];
    const float* out_b  = (const float*)d_in[11];
    float* out = (float*)d_out;

    __half *a16,*bh,*bl,*s0,*s1,*sB;
    cudaGetSymbolAddress((void**)&a16, g_A16);
    cudaGetSymbolAddress((void**)&bh,  g_Bh);  cudaGetSymbolAddress((void**)&bl, g_Bl);
    cudaGetSymbolAddress((void**)&s0,  g_S0);  cudaGetSymbolAddress((void**)&s1, g_S1);
    cudaGetSymbolAddress((void**)&sB,  g_SB);

    static int smem_set = 0;
    if (!smem_set){
        cudaFuncSetAttribute(gemm1_mma, cudaFuncAttributeMaxDynamicSharedMemorySize, SMEM_ALLOC);
        cudaFuncSetAttribute(step_mma,  cudaFuncAttributeMaxDynamicSharedMemorySize, SMEM_ALLOC);
        smem_set = 1;
    }

    // 0) converts + prep
    conv16_kernel<<<(B_SZ*FDIM/4)/256, 256>>>(conc, a16, B_SZ*FDIM/4);
    split16_kernel<<<(SDIM*FDIM/4)/256, 256>>>(f2n_w, bh, bl, SDIM*FDIM/4);
    prep_kernel<<<HID, HID>>>(msg_w, msg_b, upd_w, upd_b);

    // 1) big feature GEMM -> S0
    {
        dim3 grid(SDIM/BN, B_SZ/BM);   // (18, 128)
        gemm1_mma<<<grid, 256, SMEM_ALLOC>>>(f2n_b, logits, enc_w, enc_b, s0);
    }

    // 2) 4 GNN steps (ping-pong)
    __half *cur = s0, *nxt = s1;
    for (int step = 0; step < 4; ++step){
        sbar_kernel<<<(B_SZ*64)/256, 256>>>(cur, sB);
        dim3 grid(HID/BN, MROWS/BM);   // (2, 1152)
        step_mma<<<grid, 256, SMEM_ALLOC>>>(cur, sB, nxt);
        __half* t = cur; cur = nxt; nxt = t;
    }

    // 3) output head
    out_kernel<<<B_SZ/8, 256>>>(cur, out_w, out_b, out);
}

// round 6
// speedup vs baseline: 4.0150x; 1.1053x over previous
#include <cuda_runtime.h>
#include <cuda_fp16.h>
#include <stdint.h>
#include <math.h>

#define B_SZ   16384
#define FDIM   2048
#define HID    256
#define NN     9
#define SDIM   (NN*HID)        // 2304
#define CATK   (2*HID)         // 512
#define MROWS  (B_SZ*NN)       // 147456

#define BM 128
#define BN 128
#define BK 64                   // fp16 K elems per chunk
#define STAGES 3
#define STG_BYTES (48*1024)     // A 16KB + Bh 16KB + Bl 16KB
#define OFF_BH 16384
#define OFF_BL 32768
#define SMEM_ALLOC (STAGES*STG_BYTES + 1024)

// ---------------- device scratch (no allocation allowed) ----------------
// States are NODE-MAJOR: S[node*B_SZ + b][h]
__device__ __half g_A16[(size_t)B_SZ*FDIM];
__device__ __half g_Bh[(size_t)SDIM*FDIM], g_Bl[(size_t)SDIM*FDIM];
__device__ __half g_S0[(size_t)MROWS*HID];
__device__ __half g_S1[(size_t)MROWS*HID];
__device__ __half g_SB[(size_t)MROWS*HID];
__device__ __half g_Wh[HID*CATK], g_Wl[HID*CATK];
__device__ float g_b2[HID];

// ---------------- helpers ----------------
__device__ __forceinline__ uint32_t smem_u32(const void* p){
    uint32_t a;
    asm("{ .reg .u64 t; cvta.to.shared.u64 t, %1; cvt.u32.u64 %0, t; }" : "=r"(a) : "l"(p));
    return a;
}
__device__ __forceinline__ void cpa16(uint32_t dst, const void* src){
    asm volatile("cp.async.cg.shared.global [%0], [%1], 16;" :: "r"(dst), "l"(src) : "memory");
}
__device__ __forceinline__ void cpa_commit(){ asm volatile("cp.async.commit_group;" ::: "memory"); }
__device__ __forceinline__ void cpa_wait1(){ asm volatile("cp.async.wait_group 1;" ::: "memory"); }
__device__ __forceinline__ void cpa_wait0(){ asm volatile("cp.async.wait_group 0;" ::: "memory"); }

__device__ __forceinline__ void ldm4(uint32_t addr, uint32_t* r){
    asm volatile("ldmatrix.sync.aligned.m8n8.x4.shared.b16 {%0,%1,%2,%3}, [%4];"
        : "=r"(r[0]),"=r"(r[1]),"=r"(r[2]),"=r"(r[3]) : "r"(addr));
}
__device__ __forceinline__ void mma16816(float* d, const uint32_t* a, uint32_t b0, uint32_t b1){
    asm volatile("mma.sync.aligned.m16n8k16.row.col.f32.f16.f16.f32 "
        "{%0,%1,%2,%3}, {%4,%5,%6,%7}, {%8,%9}, {%0,%1,%2,%3};"
        : "+f"(d[0]),"+f"(d[1]),"+f"(d[2]),"+f"(d[3])
        : "r"(a[0]),"r"(a[1]),"r"(a[2]),"r"(a[3]), "r"(b0),"r"(b1));
}

__device__ __forceinline__ uint32_t a_addr(uint32_t base, int row0, int c0, int lane){
    int r = row0 + (lane & 7) + ((lane >> 3) & 1) * 8;
    int c = c0 + (lane >> 4);
    return base + r*128 + ((c ^ (r & 7)) << 4);
}
__device__ __forceinline__ uint32_t b_addr(uint32_t base, int n0, int c0, int lane){
    int r = n0 + (lane & 7) + (lane >> 4) * 8;
    int c = c0 + ((lane >> 3) & 1);
    return base + r*128 + ((c ^ (r & 7)) << 4);
}

__device__ __forceinline__ uint32_t pkh2(float a, float b){
    __half2 h = __floats2half2_rn(a, b);
    return *(uint32_t*)&h;
}
__device__ __forceinline__ float tanh_fast(float x){
    float ax = fabsf(x);
    float z = __expf(-2.f*ax);
    float y = __fdividef(1.f - z, 1.f + z);
    return copysignf(y, x);
}

__device__ __forceinline__ void load_stage(uint32_t base, int tid,
    const __half* aP, int lda, const __half* bhP, const __half* blP, int ldb)
{
    #pragma unroll
    for (int i=0;i<4;i++){
        int id = i*256 + tid;
        int row = id>>3, c = id&7;
        uint32_t d = row*128 + ((c ^ (row&7))<<4);
        cpa16(base + d, aP + (size_t)row*lda + (c<<3));
    }
    #pragma unroll
    for (int i=0;i<4;i++){
        int id = i*256 + tid;
        int row = id>>3, c = id&7;
        uint32_t d = row*128 + ((c ^ (row&7))<<4);
        cpa16(base + OFF_BH + d, bhP + (size_t)row*ldb + (c<<3));
        cpa16(base + OFF_BL + d, blP + (size_t)row*ldb + (c<<3));
    }
    cpa_commit();
}

// one 64-K chunk: 2 products A*Bh + A*Bl; warp tile 64(M) x 32(N)
__device__ __forceinline__ void compute_stage(uint32_t base, float acc[4][4][4],
                                              int warp_m, int warp_n, int lane)
{
    #pragma unroll
    for (int k16=0; k16<4; k16++){
        int c0 = 2*k16;
        uint32_t aF[4][4], bH[2][4], bL[2][4];
        #pragma unroll
        for (int mt=0; mt<4; mt++)
            ldm4(a_addr(base, warp_m + mt*16, c0, lane), aF[mt]);
        #pragma unroll
        for (int g=0; g<2; g++){
            ldm4(b_addr(base + OFF_BH, warp_n + g*16, c0, lane), bH[g]);
            ldm4(b_addr(base + OFF_BL, warp_n + g*16, c0, lane), bL[g]);
        }
        #pragma unroll
        for (int mt=0; mt<4; mt++)
            #pragma unroll
            for (int nt=0; nt<4; nt++){
                int g = nt>>1, p = (nt&1)*2;
                mma16816(acc[mt][nt], aF[mt], bH[g][p], bH[g][p+1]);
                mma16816(acc[mt][nt], aF[mt], bL[g][p], bL[g][p+1]);
            }
    }
}

// ---------------- converts / prep ----------------
__global__ void conv16_kernel(const float* __restrict__ x, __half* __restrict__ h, int n4)
{
    int i = blockIdx.x*blockDim.x + threadIdx.x;
    if (i >= n4) return;
    float4 v = ((const float4*)x)[i];
    ((uint2*)h)[i] = make_uint2(pkh2(v.x,v.y), pkh2(v.z,v.w));
}
__global__ void split16_kernel(const float* __restrict__ x,
                               __half* __restrict__ h, __half* __restrict__ l, int n4)
{
    int i = blockIdx.x*blockDim.x + threadIdx.x;
    if (i >= n4) return;
    float4 v = ((const float4*)x)[i];
    float h0 = __half2float(__float2half_rn(v.x));
    float h1 = __half2float(__float2half_rn(v.y));
    float h2 = __half2float(__float2half_rn(v.z));
    float h3 = __half2float(__float2half_rn(v.w));
    ((uint2*)h)[i] = make_uint2(pkh2(h0,h1), pkh2(h2,h3));
    ((uint2*)l)[i] = make_uint2(pkh2(v.x-h0, v.y-h1), pkh2(v.z-h2, v.w-h3));
}
__global__ void prep_kernel(const float* __restrict__ msg_w, const float* __restrict__ msg_b,
                            const float* __restrict__ upd_w, const float* __restrict__ upd_b)
{
    int o = blockIdx.x, k = threadIdx.x;
    const float* u2 = upd_w + o*CATK + HID;
    float w1 = upd_w[o*CATK + k];
    float h1 = __half2float(__float2half_rn(w1));
    g_Wh[o*CATK + k] = __float2half_rn(w1);
    g_Wl[o*CATK + k] = __float2half_rn(w1 - h1);
    float acc = 0.f;
    #pragma unroll 4
    for (int m=0;m<HID;m++) acc += u2[m]*msg_w[m*HID + k];
    float h2 = __half2float(__float2half_rn(acc));
    g_Wh[o*CATK + HID + k] = __float2half_rn(acc);
    g_Wl[o*CATK + HID + k] = __float2half_rn(acc - h2);
    if (k==0){
        float bb = upd_b[o];
        for (int m=0;m<HID;m++) bb += u2[m]*msg_b[m];
        g_b2[o] = bb;
    }
}
__global__ void init_out_kernel(float* __restrict__ out, const float* __restrict__ out_b)
{
    int i = blockIdx.x*blockDim.x + threadIdx.x;
    if (i < 2*B_SZ) out[i] = out_b[0];
}

// ---------------- GEMM1: conc @ f2n_w^T + biases + encoder -> S (node-major) ----------------
__global__ void __launch_bounds__(256,1) gemm1_mma(
    const float* __restrict__ f2n_b, const float* __restrict__ logits,
    const float* __restrict__ enc_w, const float* __restrict__ enc_b,
    __half* __restrict__ S)
{
    extern __shared__ char smraw[];
    uint32_t sb = (smem_u32(smraw) + 1023u) & ~1023u;
    const int tid = threadIdx.x, wid = tid>>5, lane = tid&31;
    const int n0 = blockIdx.x * BN;
    const int m0 = blockIdx.y * BM;
    const int node = blockIdx.x >> 1;
    const int warp_m = (wid & 1) * 64;
    const int warp_n = (wid >> 1) * 32;

    const __half* A  = g_A16 + (size_t)m0*FDIM;
    const __half* Bh = g_Bh  + (size_t)n0*FDIM;
    const __half* Bl = g_Bl  + (size_t)n0*FDIM;

    float acc[4][4][4];
    #pragma unroll
    for (int a=0;a<4;a++) for (int b=0;b<4;b++) for (int c=0;c<4;c++) acc[a][b][c]=0.f;

    load_stage(sb,             tid, A,    FDIM, Bh,    Bl,    FDIM);
    load_stage(sb+STG_BYTES,   tid, A+BK, FDIM, Bh+BK, Bl+BK, FDIM);

    const int NC = FDIM/BK;   // 32
    #pragma unroll 1
    for (int c=0;c<NC;c++){
        if (c == NC-1) cpa_wait0(); else cpa_wait1();
        __syncthreads();
        if (c+2 < NC){
            int s2 = (c+2)%STAGES;
            int kc = (c+2)*BK;
            load_stage(sb + s2*STG_BYTES, tid, A+kc, FDIM, Bh+kc, Bl+kc, FDIM);
        }
        compute_stage(sb + (c%STAGES)*STG_BYTES, acc, warp_m, warp_n, lane);
    }

    const int lane4 = lane>>2, lane2 = (lane&3)*2;
    __half* Sn = S + (size_t)node*B_SZ*HID;     // node block
    #pragma unroll
    for (int mt=0; mt<4; mt++){
        int r0 = m0 + warp_m + mt*16 + lane4;
        float lg0 = logits[(size_t)r0*NN + node];
        float lg1 = logits[(size_t)(r0+8)*NN + node];
        #pragma unroll
        for (int nt=0; nt<4; nt++){
            int cg = n0 + warp_n + nt*8 + lane2;
            int h  = cg & 255;
            float fb0 = f2n_b[cg] + enc_b[h],   fb1 = f2n_b[cg+1] + enc_b[h+1];
            float ew0 = enc_w[h],               ew1 = enc_w[h+1];
            float* a4 = acc[mt][nt];
            *(uint32_t*)(Sn + (size_t)r0*HID + h)     = pkh2(a4[0]+fb0+lg0*ew0, a4[1]+fb1+lg0*ew1);
            *(uint32_t*)(Sn + (size_t)(r0+8)*HID + h) = pkh2(a4[2]+fb0+lg1*ew0, a4[3]+fb1+lg1*ew1);
        }
    }
}

// ---------------- step GEMM (steps 1-3): tanh([S|SB] @ Wc^T + b2) -> O ----------------
__global__ void __launch_bounds__(256,1) step_mma(
    const __half* __restrict__ S, const __half* __restrict__ SB,
    __half* __restrict__ O)
{
    extern __shared__ char smraw[];
    uint32_t sb = (smem_u32(smraw) + 1023u) & ~1023u;
    const int tid = threadIdx.x, wid = tid>>5, lane = tid&31;
    const int n0 = blockIdx.x * BN;
    const int m0 = blockIdx.y * BM;
    const int warp_m = (wid & 1) * 64;
    const int warp_n = (wid >> 1) * 32;

    float acc[4][4][4];
    #pragma unroll
    for (int a=0;a<4;a++) for (int b=0;b<4;b++) for (int c=0;c<4;c++) acc[a][b][c]=0.f;

    const __half* aS  = S  + (size_t)m0*HID;
    const __half* aSB = SB + (size_t)m0*HID;
    const __half* Wh = g_Wh + (size_t)n0*CATK;
    const __half* Wl = g_Wl + (size_t)n0*CATK;

    load_stage(sb,           tid, aS,    HID, Wh,    Wl,    CATK);
    load_stage(sb+STG_BYTES, tid, aS+BK, HID, Wh+BK, Wl+BK, CATK);

    const int NC = CATK/BK;   // 8
    #pragma unroll 1
    for (int c=0;c<NC;c++){
        if (c == NC-1) cpa_wait0(); else cpa_wait1();
        __syncthreads();
        if (c+2 < NC){
            int s2 = (c+2)%STAGES;
            int kg = (c+2)*BK;
            const __half* aP = (kg < HID ? aS : aSB) + (kg & (HID-1));
            load_stage(sb + s2*STG_BYTES, tid, aP, HID, Wh+kg, Wl+kg, CATK);
        }
        compute_stage(sb + (c%STAGES)*STG_BYTES, acc, warp_m, warp_n, lane);
    }

    const int lane4 = lane>>2, lane2 = (lane&3)*2;
    #pragma unroll
    for (int mt=0; mt<4; mt++){
        int r0 = m0 + warp_m + mt*16 + lane4;
        #pragma unroll
        for (int nt=0; nt<4; nt++){
            int cg = n0 + warp_n + nt*8 + lane2;
            float b0 = g_b2[cg], b1 = g_b2[cg+1];
            float* a4 = acc[mt][nt];
            *(uint32_t*)(O + (size_t)r0*HID + cg)     = pkh2(tanh_fast(a4[0]+b0), tanh_fast(a4[1]+b1));
            *(uint32_t*)(O + (size_t)(r0+8)*HID + cg) = pkh2(tanh_fast(a4[2]+b0), tanh_fast(a4[3]+b1));
        }
    }
}

// ---------------- step 4 fused: only nodes 7/8, dot with out_w, atomic out ----------------
__global__ void __launch_bounds__(256,1) step_out_mma(
    const __half* __restrict__ S, const __half* __restrict__ SB,
    const float* __restrict__ out_w, float* __restrict__ out)
{
    extern __shared__ char smraw[];
    uint32_t sb = (smem_u32(smraw) + 1023u) & ~1023u;
    __shared__ float sums[BM];
    const int tid = threadIdx.x, wid = tid>>5, lane = tid&31;
    const int n0 = blockIdx.x * BN;
    const int m0 = 7*B_SZ + blockIdx.y * BM;   // rows of nodes 7,8 only
    const int warp_m = (wid & 1) * 64;
    const int warp_n = (wid >> 1) * 32;

    if (tid < BM) sums[tid] = 0.f;

    float acc[4][4][4];
    #pragma unroll
    for (int a=0;a<4;a++) for (int b=0;b<4;b++) for (int c=0;c<4;c++) acc[a][b][c]=0.f;

    const __half* aS  = S  + (size_t)m0*HID;
    const __half* aSB = SB + (size_t)m0*HID;
    const __half* Wh = g_Wh + (size_t)n0*CATK;
    const __half* Wl = g_Wl + (size_t)n0*CATK;

    load_stage(sb,           tid, aS,    HID, Wh,    Wl,    CATK);
    load_stage(sb+STG_BYTES, tid, aS+BK, HID, Wh+BK, Wl+BK, CATK);

    const int NC = CATK/BK;   // 8
    #pragma unroll 1
    for (int c=0;c<NC;c++){
        if (c == NC-1) cpa_wait0(); else cpa_wait1();
        __syncthreads();
        if (c+2 < NC){
            int s2 = (c+2)%STAGES;
            int kg = (c+2)*BK;
            const __half* aP = (kg < HID ? aS : aSB) + (kg & (HID-1));
            load_stage(sb + s2*STG_BYTES, tid, aP, HID, Wh+kg, Wl+kg, CATK);
        }
        compute_stage(sb + (c%STAGES)*STG_BYTES, acc, warp_m, warp_n, lane);
    }
    __syncthreads();   // sums[] initialized & pipeline done

    const int lane4 = lane>>2, lane2 = (lane&3)*2;
    #pragma unroll
    for (int mt=0; mt<4; mt++){
        int lr0 = warp_m + mt*16 + lane4;
        float p0 = 0.f, p1 = 0.f;
        #pragma unroll
        for (int nt=0; nt<4; nt++){
            int cg = n0 + warp_n + nt*8 + lane2;
            float b0 = g_b2[cg], b1 = g_b2[cg+1];
            float w0 = out_w[cg], w1 = out_w[cg+1];
            float* a4 = acc[mt][nt];
            p0 += tanh_fast(a4[0]+b0)*w0 + tanh_fast(a4[1]+b1)*w1;
            p1 += tanh_fast(a4[2]+b0)*w0 + tanh_fast(a4[3]+b1)*w1;
        }
        atomicAdd(&sums[lr0], p0);
        atomicAdd(&sums[lr0+8], p1);
    }
    __syncthreads();
    if (tid < BM){
        int gr = m0 + tid;                 // global row in [7*B_SZ, 9*B_SZ)
        int node = gr >> 14;               // 7 or 8
        int b = gr & (B_SZ-1);
        atomicAdd(&out[(node-7)*B_SZ + b], sums[tid]);
    }
}

// ---------------- adjacency aggregate (node-major) ----------------
__global__ void sbar_kernel(const __half* __restrict__ S, __half* __restrict__ SB)
{
    int idx = blockIdx.x*blockDim.x + threadIdx.x;
    if (idx >= B_SZ*64) return;
    int b = idx>>6, c4 = (idx&63)<<2;
    float s[9][4];
    #pragma unroll
    for (int n=0;n<9;n++){
        uint2 v = *(const uint2*)(S + ((size_t)n*B_SZ + b)*HID + c4);
        float2 f01 = __half22float2(*(__half2*)&v.x);
        float2 f23 = __half22float2(*(__half2*)&v.y);
        s[n][0]=f01.x; s[n][1]=f01.y; s[n][2]=f23.x; s[n][3]=f23.y;
    }
    float o[9][4];
    #pragma unroll
    for (int e=0;e<4;e++){
        float tot = 0.f;
        #pragma unroll
        for (int n=0;n<9;n++) tot += s[n][e];
        float hub = s[0][e] + s[7][e] + s[8][e];
        float m78 = (tot - s[1][e]) * 0.125f;
        o[0][e] = tot * (1.f/9.f);
        o[1][e] = (s[0][e] + s[1][e]) * 0.5f;
        #pragma unroll
        for (int n=2;n<=6;n++) o[n][e] = (hub + s[n][e]) * 0.25f;
        o[7][e] = m78; o[8][e] = m78;
    }
    #pragma unroll
    for (int n=0;n<9;n++)
        *(uint2*)(SB + ((size_t)n*B_SZ + b)*HID + c4) =
            make_uint2(pkh2(o[n][0],o[n][1]), pkh2(o[n][2],o[n][3]));
}

// step-4 aggregate: only m78, written to node-7 and node-8 blocks
__global__ void sbar78_kernel(const __half* __restrict__ S, __half* __restrict__ SB)
{
    int idx = blockIdx.x*blockDim.x + threadIdx.x;
    if (idx >= B_SZ*64) return;
    int b = idx>>6, c4 = (idx&63)<<2;
    float t0=0.f,t1=0.f,t2=0.f,t3=0.f, s10=0.f,s11=0.f,s12=0.f,s13=0.f;
    #pragma unroll
    for (int n=0;n<9;n++){
        uint2 v = *(const uint2*)(S + ((size_t)n*B_SZ + b)*HID + c4);
        float2 f01 = __half22float2(*(__half2*)&v.x);
        float2 f23 = __half22float2(*(__half2*)&v.y);
        t0+=f01.x; t1+=f01.y; t2+=f23.x; t3+=f23.y;
        if (n==1){ s10=f01.x; s11=f01.y; s12=f23.x; s13=f23.y; }
    }
    uint2 m = make_uint2(pkh2((t0-s10)*0.125f, (t1-s11)*0.125f),
                         pkh2((t2-s12)*0.125f, (t3-s13)*0.125f));
    *(uint2*)(SB + ((size_t)7*B_SZ + b)*HID + c4) = m;
    *(uint2*)(SB + ((size_t)8*B_SZ + b)*HID + c4) = m;
}

// ---------------- launch ----------------
extern "C" void kernel_launch(void* const* d_in, const int* in_sizes, int n_in,
                              void* d_out, int out_size)
{
    (void)in_sizes; (void)n_in; (void)out_size;
    const float* conc   = (const float*)d_in[0];
    const float* logits = (const float*)d_in[1];
    const float* enc_w  = (const float*)d_in[2];
    const float* enc_b  = (const float*)d_in[3];
    const float* f2n_w  = (const float*)d_in[4];
    const float* f2n_b  = (const float*)d_in[5];
    const float* msg_w  = (const float*)d_in[6];
    const float* msg_b  = (const float*)d_in[7];
    const float* upd_w  = (const float*)d_in[8];
    const float* upd_b  = (const float*)d_in[9];
    const float* out_w  = (const float*)d_in[10];
    const float* out_b  = (const float*)d_in[11];
    float* out = (float*)d_out;

    __half *a16,*bh,*bl,*s0,*s1,*sB;
    cudaGetSymbolAddress((void**)&a16, g_A16);
    cudaGetSymbolAddress((void**)&bh,  g_Bh);  cudaGetSymbolAddress((void**)&bl, g_Bl);
    cudaGetSymbolAddress((void**)&s0,  g_S0);  cudaGetSymbolAddress((void**)&s1, g_S1);
    cudaGetSymbolAddress((void**)&sB,  g_SB);

    static int smem_set = 0;
    if (!smem_set){
        cudaFuncSetAttribute(gemm1_mma,    cudaFuncAttributeMaxDynamicSharedMemorySize, SMEM_ALLOC);
        cudaFuncSetAttribute(step_mma,     cudaFuncAttributeMaxDynamicSharedMemorySize, SMEM_ALLOC);
        cudaFuncSetAttribute(step_out_mma, cudaFuncAttributeMaxDynamicSharedMemorySize, SMEM_ALLOC);
        smem_set = 1;
    }

    // 0) converts + prep + out init
    conv16_kernel<<<(B_SZ*FDIM/4)/256, 256>>>(conc, a16, B_SZ*FDIM/4);
    split16_kernel<<<(SDIM*FDIM/4)/256, 256>>>(f2n_w, bh, bl, SDIM*FDIM/4);
    prep_kernel<<<HID, HID>>>(msg_w, msg_b, upd_w, upd_b);
    init_out_kernel<<<(2*B_SZ)/256, 256>>>(out, out_b);

    // 1) big feature GEMM -> S0 (node-major)
    {
        dim3 grid(SDIM/BN, B_SZ/BM);   // (18, 128)
        gemm1_mma<<<grid, 256, SMEM_ALLOC>>>(f2n_b, logits, enc_w, enc_b, s0);
    }

    // 2) steps 1-3 (ping-pong)
    __half *cur = s0, *nxt = s1;
    for (int step = 0; step < 3; ++step){
        sbar_kernel<<<(B_SZ*64)/256, 256>>>(cur, sB);
        dim3 grid(HID/BN, MROWS/BM);   // (2, 1152)
        step_mma<<<grid, 256, SMEM_ALLOC>>>(cur, sB, nxt);
        __half* t = cur; cur = nxt; nxt = t;
    }

    // 3) step 4 fused with output head (nodes 7,8 only)
    sbar78_kernel<<<(B_SZ*64)/256, 256>>>(cur, sB);
    {
        dim3 grid(HID/BN, 2*B_SZ/BM);  // (2, 256)
        step_out_mma<<<grid, 256, SMEM_ALLOC>>>(cur, sB, out_w, out);
    }
}

// round 7
// speedup vs baseline: 5.1335x; 1.2786x over previous
#include <cuda_runtime.h>
#include <cuda_fp16.h>
#include <stdint.h>
#include <math.h>

#define B_SZ   16384
#define FDIM   2048
#define HID    256
#define NN     9
#define SDIM   (NN*HID)        // 2304
#define CATK   (2*HID)         // 512
#define MROWS  (B_SZ*NN)       // 147456

// ---- step-GEMM tile (2-product, proven) ----
#define BM 128
#define BN 128
#define BK 64
#define STAGES 3
#define STG_BYTES (48*1024)
#define OFF_BH 16384
#define OFF_BL 32768
#define SMEM_ALLOC (STAGES*STG_BYTES + 1024)

// ---- gemm1 tile (1-product, BN=256) ----
#define BN1 256
#define OFF_B1 16384
#define STG1_BYTES (48*1024)    // A 16KB + B 32KB
#define SMEM1_ALLOC (STAGES*STG1_BYTES + 1024)

// ---------------- device scratch (no allocation allowed) ----------------
// States are NODE-MAJOR: S[node*B_SZ + b][h]
__device__ __half g_A16[(size_t)B_SZ*FDIM];
__device__ __half g_B16[(size_t)SDIM*FDIM];
__device__ __half g_S0[(size_t)MROWS*HID];
__device__ __half g_S1[(size_t)MROWS*HID];
__device__ __half g_SB[(size_t)MROWS*HID];
__device__ __half g_Wh[HID*CATK], g_Wl[HID*CATK];
__device__ float g_b2[HID];

// ---------------- helpers ----------------
__device__ __forceinline__ uint32_t smem_u32(const void* p){
    uint32_t a;
    asm("{ .reg .u64 t; cvta.to.shared.u64 t, %1; cvt.u32.u64 %0, t; }" : "=r"(a) : "l"(p));
    return a;
}
__device__ __forceinline__ void cpa16(uint32_t dst, const void* src){
    asm volatile("cp.async.cg.shared.global [%0], [%1], 16;" :: "r"(dst), "l"(src) : "memory");
}
__device__ __forceinline__ void cpa_commit(){ asm volatile("cp.async.commit_group;" ::: "memory"); }
__device__ __forceinline__ void cpa_wait1(){ asm volatile("cp.async.wait_group 1;" ::: "memory"); }
__device__ __forceinline__ void cpa_wait0(){ asm volatile("cp.async.wait_group 0;" ::: "memory"); }

__device__ __forceinline__ void ldm4(uint32_t addr, uint32_t* r){
    asm volatile("ldmatrix.sync.aligned.m8n8.x4.shared.b16 {%0,%1,%2,%3}, [%4];"
        : "=r"(r[0]),"=r"(r[1]),"=r"(r[2]),"=r"(r[3]) : "r"(addr));
}
__device__ __forceinline__ void mma16816(float* d, const uint32_t* a, uint32_t b0, uint32_t b1){
    asm volatile("mma.sync.aligned.m16n8k16.row.col.f32.f16.f16.f32 "
        "{%0,%1,%2,%3}, {%4,%5,%6,%7}, {%8,%9}, {%0,%1,%2,%3};"
        : "+f"(d[0]),"+f"(d[1]),"+f"(d[2]),"+f"(d[3])
        : "r"(a[0]),"r"(a[1]),"r"(a[2]),"r"(a[3]), "r"(b0),"r"(b1));
}

__device__ __forceinline__ uint32_t a_addr(uint32_t base, int row0, int c0, int lane){
    int r = row0 + (lane & 7) + ((lane >> 3) & 1) * 8;
    int c = c0 + (lane >> 4);
    return base + r*128 + ((c ^ (r & 7)) << 4);
}
__device__ __forceinline__ uint32_t b_addr(uint32_t base, int n0, int c0, int lane){
    int r = n0 + (lane & 7) + (lane >> 4) * 8;
    int c = c0 + ((lane >> 3) & 1);
    return base + r*128 + ((c ^ (r & 7)) << 4);
}

__device__ __forceinline__ uint32_t pkh2(float a, float b){
    __half2 h = __floats2half2_rn(a, b);
    return *(uint32_t*)&h;
}
__device__ __forceinline__ float tanh_fast(float x){
    float ax = fabsf(x);
    float z = __expf(-2.f*ax);
    float y = __fdividef(1.f - z, 1.f + z);
    return copysignf(y, x);
}

// ======== gemm1 (1-product, 128x256 tile) ========
__device__ __forceinline__ void load_stage1(uint32_t base, int tid,
    const __half* aP, int lda, const __half* bP, int ldb)
{
    #pragma unroll
    for (int i=0;i<4;i++){
        int id = i*256 + tid;
        int row = id>>3, c = id&7;
        cpa16(base + row*128 + ((c ^ (row&7))<<4), aP + (size_t)row*lda + (c<<3));
    }
    #pragma unroll
    for (int i=0;i<8;i++){
        int id = i*256 + tid;
        int row = id>>3, c = id&7;
        cpa16(base + OFF_B1 + row*128 + ((c ^ (row&7))<<4), bP + (size_t)row*ldb + (c<<3));
    }
    cpa_commit();
}

__device__ __forceinline__ void compute_stage1(uint32_t base, float acc[4][8][4],
                                               int warp_m, int warp_n, int lane)
{
    #pragma unroll
    for (int k16=0; k16<4; k16++){
        int c0 = 2*k16;
        uint32_t aF[4][4], bF[4][4];
        #pragma unroll
        for (int mt=0; mt<4; mt++)
            ldm4(a_addr(base, warp_m + mt*16, c0, lane), aF[mt]);
        #pragma unroll
        for (int g=0; g<4; g++)
            ldm4(b_addr(base + OFF_B1, warp_n + g*16, c0, lane), bF[g]);
        #pragma unroll
        for (int mt=0; mt<4; mt++)
            #pragma unroll
            for (int nt=0; nt<8; nt++){
                int g = nt>>1, p = (nt&1)*2;
                mma16816(acc[mt][nt], aF[mt], bF[g][p], bF[g][p+1]);
            }
    }
}

// ======== step GEMM pieces (2-product, 128x128 tile) ========
__device__ __forceinline__ void load_stage(uint32_t base, int tid,
    const __half* aP, int lda, const __half* bhP, const __half* blP, int ldb)
{
    #pragma unroll
    for (int i=0;i<4;i++){
        int id = i*256 + tid;
        int row = id>>3, c = id&7;
        uint32_t d = row*128 + ((c ^ (row&7))<<4);
        cpa16(base + d, aP + (size_t)row*lda + (c<<3));
    }
    #pragma unroll
    for (int i=0;i<4;i++){
        int id = i*256 + tid;
        int row = id>>3, c = id&7;
        uint32_t d = row*128 + ((c ^ (row&7))<<4);
        cpa16(base + OFF_BH + d, bhP + (size_t)row*ldb + (c<<3));
        cpa16(base + OFF_BL + d, blP + (size_t)row*ldb + (c<<3));
    }
    cpa_commit();
}

__device__ __forceinline__ void compute_stage(uint32_t base, float acc[4][4][4],
                                              int warp_m, int warp_n, int lane)
{
    #pragma unroll
    for (int k16=0; k16<4; k16++){
        int c0 = 2*k16;
        uint32_t aF[4][4], bH[2][4], bL[2][4];
        #pragma unroll
        for (int mt=0; mt<4; mt++)
            ldm4(a_addr(base, warp_m + mt*16, c0, lane), aF[mt]);
        #pragma unroll
        for (int g=0; g<2; g++){
            ldm4(b_addr(base + OFF_BH, warp_n + g*16, c0, lane), bH[g]);
            ldm4(b_addr(base + OFF_BL, warp_n + g*16, c0, lane), bL[g]);
        }
        #pragma unroll
        for (int mt=0; mt<4; mt++)
            #pragma unroll
            for (int nt=0; nt<4; nt++){
                int g = nt>>1, p = (nt&1)*2;
                mma16816(acc[mt][nt], aF[mt], bH[g][p], bH[g][p+1]);
                mma16816(acc[mt][nt], aF[mt], bL[g][p], bL[g][p+1]);
            }
    }
}

// ---------------- converts / prep ----------------
__global__ void conv16_kernel(const float* __restrict__ x, __half* __restrict__ h, int n4)
{
    int i = blockIdx.x*blockDim.x + threadIdx.x;
    if (i >= n4) return;
    float4 v = ((const float4*)x)[i];
    ((uint2*)h)[i] = make_uint2(pkh2(v.x,v.y), pkh2(v.z,v.w));
}
__global__ void prep_kernel(const float* __restrict__ msg_w, const float* __restrict__ msg_b,
                            const float* __restrict__ upd_w, const float* __restrict__ upd_b)
{
    int o = blockIdx.x, k = threadIdx.x;
    const float* u2 = upd_w + o*CATK + HID;
    float w1 = upd_w[o*CATK + k];
    float h1 = __half2float(__float2half_rn(w1));
    g_Wh[o*CATK + k] = __float2half_rn(w1);
    g_Wl[o*CATK + k] = __float2half_rn(w1 - h1);
    float acc = 0.f;
    #pragma unroll 4
    for (int m=0;m<HID;m++) acc += u2[m]*msg_w[m*HID + k];
    float h2 = __half2float(__float2half_rn(acc));
    g_Wh[o*CATK + HID + k] = __float2half_rn(acc);
    g_Wl[o*CATK + HID + k] = __float2half_rn(acc - h2);
    if (k==0){
        float bb = upd_b[o];
        for (int m=0;m<HID;m++) bb += u2[m]*msg_b[m];
        g_b2[o] = bb;
    }
}
__global__ void init_out_kernel(float* __restrict__ out, const float* __restrict__ out_b)
{
    int i = blockIdx.x*blockDim.x + threadIdx.x;
    if (i < 2*B_SZ) out[i] = out_b[0];
}

// ---------------- GEMM1: conc @ f2n_w^T + biases + encoder -> S (node-major) ----------------
__global__ void __launch_bounds__(256,1) gemm1_mma(
    const float* __restrict__ f2n_b, const float* __restrict__ logits,
    const float* __restrict__ enc_w, const float* __restrict__ enc_b,
    __half* __restrict__ S)
{
    extern __shared__ char smraw[];
    uint32_t sb = (smem_u32(smraw) + 1023u) & ~1023u;
    const int tid = threadIdx.x, wid = tid>>5, lane = tid&31;
    const int node = blockIdx.x;            // one node per CTA (BN1=256)
    const int n0 = node * BN1;
    const int m0 = blockIdx.y * BM;
    const int warp_m = (wid & 1) * 64;
    const int warp_n = (wid >> 1) * 64;

    const __half* A = g_A16 + (size_t)m0*FDIM;
    const __half* B = g_B16 + (size_t)n0*FDIM;

    float acc[4][8][4];
    #pragma unroll
    for (int a=0;a<4;a++) for (int b=0;b<8;b++) for (int c=0;c<4;c++) acc[a][b][c]=0.f;

    load_stage1(sb,              tid, A,    FDIM, B,    FDIM);
    load_stage1(sb+STG1_BYTES,   tid, A+BK, FDIM, B+BK, FDIM);

    const int NC = FDIM/BK;   // 32
    #pragma unroll 1
    for (int c=0;c<NC;c++){
        if (c == NC-1) cpa_wait0(); else cpa_wait1();
        __syncthreads();
        if (c+2 < NC){
            int s2 = (c+2)%STAGES;
            int kc = (c+2)*BK;
            load_stage1(sb + s2*STG1_BYTES, tid, A+kc, FDIM, B+kc, FDIM);
        }
        compute_stage1(sb + (c%STAGES)*STG1_BYTES, acc, warp_m, warp_n, lane);
    }

    const int lane4 = lane>>2, lane2 = (lane&3)*2;
    __half* Sn = S + (size_t)node*B_SZ*HID;
    #pragma unroll
    for (int mt=0; mt<4; mt++){
        int r0 = m0 + warp_m + mt*16 + lane4;
        float lg0 = logits[(size_t)r0*NN + node];
        float lg1 = logits[(size_t)(r0+8)*NN + node];
        #pragma unroll
        for (int nt=0; nt<8; nt++){
            int h = warp_n + nt*8 + lane2;           // 0..255
            float fb0 = f2n_b[n0+h] + enc_b[h],   fb1 = f2n_b[n0+h+1] + enc_b[h+1];
            float ew0 = enc_w[h],                 ew1 = enc_w[h+1];
            float* a4 = acc[mt][nt];
            *(uint32_t*)(Sn + (size_t)r0*HID + h)     = pkh2(a4[0]+fb0+lg0*ew0, a4[1]+fb1+lg0*ew1);
            *(uint32_t*)(Sn + (size_t)(r0+8)*HID + h) = pkh2(a4[2]+fb0+lg1*ew0, a4[3]+fb1+lg1*ew1);
        }
    }
}

// ---------------- step GEMM (steps 1-3): tanh([S|SB] @ Wc^T + b2) -> O ----------------
__global__ void __launch_bounds__(256,1) step_mma(
    const __half* __restrict__ S, const __half* __restrict__ SB,
    __half* __restrict__ O)
{
    extern __shared__ char smraw[];
    uint32_t sb = (smem_u32(smraw) + 1023u) & ~1023u;
    const int tid = threadIdx.x, wid = tid>>5, lane = tid&31;
    const int n0 = blockIdx.x * BN;
    const int m0 = blockIdx.y * BM;
    const int warp_m = (wid & 1) * 64;
    const int warp_n = (wid >> 1) * 32;

    float acc[4][4][4];
    #pragma unroll
    for (int a=0;a<4;a++) for (int b=0;b<4;b++) for (int c=0;c<4;c++) acc[a][b][c]=0.f;

    const __half* aS  = S  + (size_t)m0*HID;
    const __half* aSB = SB + (size_t)m0*HID;
    const __half* Wh = g_Wh + (size_t)n0*CATK;
    const __half* Wl = g_Wl + (size_t)n0*CATK;

    load_stage(sb,           tid, aS,    HID, Wh,    Wl,    CATK);
    load_stage(sb+STG_BYTES, tid, aS+BK, HID, Wh+BK, Wl+BK, CATK);

    const int NC = CATK/BK;   // 8
    #pragma unroll 1
    for (int c=0;c<NC;c++){
        if (c == NC-1) cpa_wait0(); else cpa_wait1();
        __syncthreads();
        if (c+2 < NC){
            int s2 = (c+2)%STAGES;
            int kg = (c+2)*BK;
            const __half* aP = (kg < HID ? aS : aSB) + (kg & (HID-1));
            load_stage(sb + s2*STG_BYTES, tid, aP, HID, Wh+kg, Wl+kg, CATK);
        }
        compute_stage(sb + (c%STAGES)*STG_BYTES, acc, warp_m, warp_n, lane);
    }

    const int lane4 = lane>>2, lane2 = (lane&3)*2;
    #pragma unroll
    for (int mt=0; mt<4; mt++){
        int r0 = m0 + warp_m + mt*16 + lane4;
        #pragma unroll
        for (int nt=0; nt<4; nt++){
            int cg = n0 + warp_n + nt*8 + lane2;
            float b0 = g_b2[cg], b1 = g_b2[cg+1];
            float* a4 = acc[mt][nt];
            *(uint32_t*)(O + (size_t)r0*HID + cg)     = pkh2(tanh_fast(a4[0]+b0), tanh_fast(a4[1]+b1));
            *(uint32_t*)(O + (size_t)(r0+8)*HID + cg) = pkh2(tanh_fast(a4[2]+b0), tanh_fast(a4[3]+b1));
        }
    }
}

// ---------------- step 4 fused: only nodes 7/8, dot with out_w, atomic out ----------------
__global__ void __launch_bounds__(256,1) step_out_mma(
    const __half* __restrict__ S, const __half* __restrict__ SB,
    const float* __restrict__ out_w, float* __restrict__ out)
{
    extern __shared__ char smraw[];
    uint32_t sb = (smem_u32(smraw) + 1023u) & ~1023u;
    __shared__ float sums[BM];
    const int tid = threadIdx.x, wid = tid>>5, lane = tid&31;
    const int n0 = blockIdx.x * BN;
    const int m0 = 7*B_SZ + blockIdx.y * BM;
    const int warp_m = (wid & 1) * 64;
    const int warp_n = (wid >> 1) * 32;

    if (tid < BM) sums[tid] = 0.f;

    float acc[4][4][4];
    #pragma unroll
    for (int a=0;a<4;a++) for (int b=0;b<4;b++) for (int c=0;c<4;c++) acc[a][b][c]=0.f;

    const __half* aS  = S  + (size_t)m0*HID;
    const __half* aSB = SB + (size_t)m0*HID;
    const __half* Wh = g_Wh + (size_t)n0*CATK;
    const __half* Wl = g_Wl + (size_t)n0*CATK;

    load_stage(sb,           tid, aS,    HID, Wh,    Wl,    CATK);
    load_stage(sb+STG_BYTES, tid, aS+BK, HID, Wh+BK, Wl+BK, CATK);

    const int NC = CATK/BK;   // 8
    #pragma unroll 1
    for (int c=0;c<NC;c++){
        if (c == NC-1) cpa_wait0(); else cpa_wait1();
        __syncthreads();
        if (c+2 < NC){
            int s2 = (c+2)%STAGES;
            int kg = (c+2)*BK;
            const __half* aP = (kg < HID ? aS : aSB) + (kg & (HID-1));
            load_stage(sb + s2*STG_BYTES, tid, aP, HID, Wh+kg, Wl+kg, CATK);
        }
        compute_stage(sb + (c%STAGES)*STG_BYTES, acc, warp_m, warp_n, lane);
    }
    __syncthreads();

    const int lane4 = lane>>2, lane2 = (lane&3)*2;
    #pragma unroll
    for (int mt=0; mt<4; mt++){
        int lr0 = warp_m + mt*16 + lane4;
        float p0 = 0.f, p1 = 0.f;
        #pragma unroll
        for (int nt=0; nt<4; nt++){
            int cg = n0 + warp_n + nt*8 + lane2;
            float b0 = g_b2[cg], b1 = g_b2[cg+1];
            float w0 = out_w[cg], w1 = out_w[cg+1];
            float* a4 = acc[mt][nt];
            p0 += tanh_fast(a4[0]+b0)*w0 + tanh_fast(a4[1]+b1)*w1;
            p1 += tanh_fast(a4[2]+b0)*w0 + tanh_fast(a4[3]+b1)*w1;
        }
        atomicAdd(&sums[lr0], p0);
        atomicAdd(&sums[lr0+8], p1);
    }
    __syncthreads();
    if (tid < BM){
        int gr = m0 + tid;
        int node = gr >> 14;               // 7 or 8
        int b = gr & (B_SZ-1);
        atomicAdd(&out[(node-7)*B_SZ + b], sums[tid]);
    }
}

// ---------------- adjacency aggregate (node-major) ----------------
__global__ void sbar_kernel(const __half* __restrict__ S, __half* __restrict__ SB)
{
    int idx = blockIdx.x*blockDim.x + threadIdx.x;
    if (idx >= B_SZ*64) return;
    int b = idx>>6, c4 = (idx&63)<<2;
    float s[9][4];
    #pragma unroll
    for (int n=0;n<9;n++){
        uint2 v = *(const uint2*)(S + ((size_t)n*B_SZ + b)*HID + c4);
        float2 f01 = __half22float2(*(__half2*)&v.x);
        float2 f23 = __half22float2(*(__half2*)&v.y);
        s[n][0]=f01.x; s[n][1]=f01.y; s[n][2]=f23.x; s[n][3]=f23.y;
    }
    float o[9][4];
    #pragma unroll
    for (int e=0;e<4;e++){
        float tot = 0.f;
        #pragma unroll
        for (int n=0;n<9;n++) tot += s[n][e];
        float hub = s[0][e] + s[7][e] + s[8][e];
        float m78 = (tot - s[1][e]) * 0.125f;
        o[0][e] = tot * (1.f/9.f);
        o[1][e] = (s[0][e] + s[1][e]) * 0.5f;
        #pragma unroll
        for (int n=2;n<=6;n++) o[n][e] = (hub + s[n][e]) * 0.25f;
        o[7][e] = m78; o[8][e] = m78;
    }
    #pragma unroll
    for (int n=0;n<9;n++)
        *(uint2*)(SB + ((size_t)n*B_SZ + b)*HID + c4) =
            make_uint2(pkh2(o[n][0],o[n][1]), pkh2(o[n][2],o[n][3]));
}

__global__ void sbar78_kernel(const __half* __restrict__ S, __half* __restrict__ SB)
{
    int idx = blockIdx.x*blockDim.x + threadIdx.x;
    if (idx >= B_SZ*64) return;
    int b = idx>>6, c4 = (idx&63)<<2;
    float t0=0.f,t1=0.f,t2=0.f,t3=0.f, s10=0.f,s11=0.f,s12=0.f,s13=0.f;
    #pragma unroll
    for (int n=0;n<9;n++){
        uint2 v = *(const uint2*)(S + ((size_t)n*B_SZ + b)*HID + c4);
        float2 f01 = __half22float2(*(__half2*)&v.x);
        float2 f23 = __half22float2(*(__half2*)&v.y);
        t0+=f01.x; t1+=f01.y; t2+=f23.x; t3+=f23.y;
        if (n==1){ s10=f01.x; s11=f01.y; s12=f23.x; s13=f23.y; }
    }
    uint2 m = make_uint2(pkh2((t0-s10)*0.125f, (t1-s11)*0.125f),
                         pkh2((t2-s12)*0.125f, (t3-s13)*0.125f));
    *(uint2*)(SB + ((size_t)7*B_SZ + b)*HID + c4) = m;
    *(uint2*)(SB + ((size_t)8*B_SZ + b)*HID + c4) = m;
}

// ---------------- launch ----------------
extern "C" void kernel_launch(void* const* d_in, const int* in_sizes, int n_in,
                              void* d_out, int out_size)
{
    (void)in_sizes; (void)n_in; (void)out_size;
    const float* conc   = (const float*)d_in[0];
    const float* logits = (const float*)d_in[1];
    const float* enc_w  = (const float*)d_in[2];
    const float* enc_b  = (const float*)d_in[3];
    const float* f2n_w  = (const float*)d_in[4];
    const float* f2n_b  = (const float*)d_in[5];
    const float* msg_w  = (const float*)d_in[6];
    const float* msg_b  = (const float*)d_in[7];
    const float* upd_w  = (const float*)d_in[8];
    const float* upd_b  = (const float*)d_in[9];
    const float* out_w  = (const float*)d_in[10];
    const float* out_b  = (const float*)d_in[11];
    float* out = (float*)d_out;

    __half *a16,*b16,*s0,*s1,*sB;
    cudaGetSymbolAddress((void**)&a16, g_A16);
    cudaGetSymbolAddress((void**)&b16, g_B16);
    cudaGetSymbolAddress((void**)&s0,  g_S0);  cudaGetSymbolAddress((void**)&s1, g_S1);
    cudaGetSymbolAddress((void**)&sB,  g_SB);

    static int smem_set = 0;
    if (!smem_set){
        cudaFuncSetAttribute(gemm1_mma,    cudaFuncAttributeMaxDynamicSharedMemorySize, SMEM1_ALLOC);
        cudaFuncSetAttribute(step_mma,     cudaFuncAttributeMaxDynamicSharedMemorySize, SMEM_ALLOC);
        cudaFuncSetAttribute(step_out_mma, cudaFuncAttributeMaxDynamicSharedMemorySize, SMEM_ALLOC);
        smem_set = 1;
    }

    // 0) converts + prep + out init
    conv16_kernel<<<(B_SZ*FDIM/4)/256, 256>>>(conc, a16, B_SZ*FDIM/4);
    conv16_kernel<<<(SDIM*FDIM/4)/256, 256>>>(f2n_w, b16, SDIM*FDIM/4);
    prep_kernel<<<HID, HID>>>(msg_w, msg_b, upd_w, upd_b);
    init_out_kernel<<<(2*B_SZ)/256, 256>>>(out, out_b);

    // 1) big feature GEMM -> S0 (node-major), 1-product fp16
    {
        dim3 grid(NN, B_SZ/BM);   // (9, 128)
        gemm1_mma<<<grid, 256, SMEM1_ALLOC>>>(f2n_b, logits, enc_w, enc_b, s0);
    }

    // 2) steps 1-3 (ping-pong)
    __half *cur = s0, *nxt = s1;
    for (int step = 0; step < 3; ++step){
        sbar_kernel<<<(B_SZ*64)/256, 256>>>(cur, sB);
        dim3 grid(HID/BN, MROWS/BM);   // (2, 1152)
        step_mma<<<grid, 256, SMEM_ALLOC>>>(cur, sB, nxt);
        __half* t = cur; cur = nxt; nxt = t;
    }

    // 3) step 4 fused with output head (nodes 7,8 only)
    sbar78_kernel<<<(B_SZ*64)/256, 256>>>(cur, sB);
    {
        dim3 grid(HID/BN, 2*B_SZ/BM);  // (2, 256)
        step_out_mma<<<grid, 256, SMEM_ALLOC>>>(cur, sB, out_w, out);
    }
}

// round 8
// speedup vs baseline: 6.6515x; 1.2957x over previous
#include <cuda_runtime.h>
#include <cuda_fp16.h>
#include <stdint.h>
#include <math.h>

#define B_SZ   16384
#define FDIM   2048
#define HID    256
#define NN     9
#define SDIM   (NN*HID)        // 2304
#define CATK   (2*HID)         // 512
#define MROWS  (B_SZ*NN)       // 147456

#define BM 128
#define BN1 256
#define BK 64
#define STAGES 3
#define OFF_B1 16384
#define STG1_BYTES (48*1024)    // A 16KB + B 32KB
#define SMEM1_ALLOC (STAGES*STG1_BYTES + 1024)

// ---------------- device scratch (no allocation allowed) ----------------
// States NODE-MAJOR: S[node*B_SZ + b][h]
__device__ __half g_A16[(size_t)B_SZ*FDIM];
__device__ __half g_B16[(size_t)SDIM*FDIM];
__device__ __half g_S0[(size_t)MROWS*HID];
__device__ __half g_S1[(size_t)MROWS*HID];
__device__ __half g_SB[(size_t)MROWS*HID];
__device__ __half g_Wc16[HID*CATK];
__device__ float g_b2[HID];

// ---------------- helpers ----------------
__device__ __forceinline__ uint32_t smem_u32(const void* p){
    uint32_t a;
    asm("{ .reg .u64 t; cvta.to.shared.u64 t, %1; cvt.u32.u64 %0, t; }" : "=r"(a) : "l"(p));
    return a;
}
__device__ __forceinline__ void cpa16(uint32_t dst, const void* src){
    asm volatile("cp.async.cg.shared.global [%0], [%1], 16;" :: "r"(dst), "l"(src) : "memory");
}
__device__ __forceinline__ void cpa_commit(){ asm volatile("cp.async.commit_group;" ::: "memory"); }
__device__ __forceinline__ void cpa_wait1(){ asm volatile("cp.async.wait_group 1;" ::: "memory"); }
__device__ __forceinline__ void cpa_wait0(){ asm volatile("cp.async.wait_group 0;" ::: "memory"); }

__device__ __forceinline__ void ldm4(uint32_t addr, uint32_t* r){
    asm volatile("ldmatrix.sync.aligned.m8n8.x4.shared.b16 {%0,%1,%2,%3}, [%4];"
        : "=r"(r[0]),"=r"(r[1]),"=r"(r[2]),"=r"(r[3]) : "r"(addr));
}
__device__ __forceinline__ void mma16816(float* d, const uint32_t* a, uint32_t b0, uint32_t b1){
    asm volatile("mma.sync.aligned.m16n8k16.row.col.f32.f16.f16.f32 "
        "{%0,%1,%2,%3}, {%4,%5,%6,%7}, {%8,%9}, {%0,%1,%2,%3};"
        : "+f"(d[0]),"+f"(d[1]),"+f"(d[2]),"+f"(d[3])
        : "r"(a[0]),"r"(a[1]),"r"(a[2]),"r"(a[3]), "r"(b0),"r"(b1));
}

__device__ __forceinline__ uint32_t a_addr(uint32_t base, int row0, int c0, int lane){
    int r = row0 + (lane & 7) + ((lane >> 3) & 1) * 8;
    int c = c0 + (lane >> 4);
    return base + r*128 + ((c ^ (r & 7)) << 4);
}
__device__ __forceinline__ uint32_t b_addr(uint32_t base, int n0, int c0, int lane){
    int r = n0 + (lane & 7) + (lane >> 4) * 8;
    int c = c0 + ((lane >> 3) & 1);
    return base + r*128 + ((c ^ (r & 7)) << 4);
}

__device__ __forceinline__ uint32_t pkh2(float a, float b){
    __half2 h = __floats2half2_rn(a, b);
    return *(uint32_t*)&h;
}
__device__ __forceinline__ float tanh_fast(float x){
    float ax = fabsf(x);
    float z = __expf(-2.f*ax);
    float y = __fdividef(1.f - z, 1.f + z);
    return copysignf(y, x);
}

// ======== shared tile machinery (1-product, 128x256 CTA tile) ========
__device__ __forceinline__ void load_stage1(uint32_t base, int tid,
    const __half* aP, int lda, const __half* bP, int ldb)
{
    #pragma unroll
    for (int i=0;i<4;i++){
        int id = i*256 + tid;
        int row = id>>3, c = id&7;
        cpa16(base + row*128 + ((c ^ (row&7))<<4), aP + (size_t)row*lda + (c<<3));
    }
    #pragma unroll
    for (int i=0;i<8;i++){
        int id = i*256 + tid;
        int row = id>>3, c = id&7;
        cpa16(base + OFF_B1 + row*128 + ((c ^ (row&7))<<4), bP + (size_t)row*ldb + (c<<3));
    }
    cpa_commit();
}

__device__ __forceinline__ void compute_stage1(uint32_t base, float acc[4][8][4],
                                               int warp_m, int warp_n, int lane)
{
    #pragma unroll
    for (int k16=0; k16<4; k16++){
        int c0 = 2*k16;
        uint32_t aF[4][4], bF[4][4];
        #pragma unroll
        for (int mt=0; mt<4; mt++)
            ldm4(a_addr(base, warp_m + mt*16, c0, lane), aF[mt]);
        #pragma unroll
        for (int g=0; g<4; g++)
            ldm4(b_addr(base + OFF_B1, warp_n + g*16, c0, lane), bF[g]);
        #pragma unroll
        for (int mt=0; mt<4; mt++)
            #pragma unroll
            for (int nt=0; nt<8; nt++){
                int g = nt>>1, p = (nt&1)*2;
                mma16816(acc[mt][nt], aF[mt], bF[g][p], bF[g][p+1]);
            }
    }
}

// ---------------- converts / prep ----------------
__global__ void conv16_kernel(const float* __restrict__ x, __half* __restrict__ h, int n4)
{
    int i = blockIdx.x*blockDim.x + threadIdx.x;
    if (i >= n4) return;
    float4 v = ((const float4*)x)[i];
    ((uint2*)h)[i] = make_uint2(pkh2(v.x,v.y), pkh2(v.z,v.w));
}
__global__ void prep_kernel(const float* __restrict__ msg_w, const float* __restrict__ msg_b,
                            const float* __restrict__ upd_w, const float* __restrict__ upd_b)
{
    int o = blockIdx.x, k = threadIdx.x;
    const float* u2 = upd_w + o*CATK + HID;
    g_Wc16[o*CATK + k] = __float2half_rn(upd_w[o*CATK + k]);
    float acc = 0.f;
    #pragma unroll 4
    for (int m=0;m<HID;m++) acc += u2[m]*msg_w[m*HID + k];
    g_Wc16[o*CATK + HID + k] = __float2half_rn(acc);
    if (k==0){
        float bb = upd_b[o];
        for (int m=0;m<HID;m++) bb += u2[m]*msg_b[m];
        g_b2[o] = bb;
    }
}
__global__ void init_out_kernel(float* __restrict__ out, const float* __restrict__ out_b)
{
    int i = blockIdx.x*blockDim.x + threadIdx.x;
    if (i < 2*B_SZ) out[i] = out_b[0];
}

// ---------------- GEMM1: conc @ f2n_w^T + biases + encoder -> S (node-major) ----------------
__global__ void __launch_bounds__(256,1) gemm1_mma(
    const float* __restrict__ f2n_b, const float* __restrict__ logits,
    const float* __restrict__ enc_w, const float* __restrict__ enc_b,
    __half* __restrict__ S)
{
    extern __shared__ char smraw[];
    uint32_t sb = (smem_u32(smraw) + 1023u) & ~1023u;
    const int tid = threadIdx.x, wid = tid>>5, lane = tid&31;
    const int node = blockIdx.x;
    const int n0 = node * BN1;
    const int m0 = blockIdx.y * BM;
    const int warp_m = (wid & 1) * 64;
    const int warp_n = (wid >> 1) * 64;

    const __half* A = g_A16 + (size_t)m0*FDIM;
    const __half* B = g_B16 + (size_t)n0*FDIM;

    float acc[4][8][4];
    #pragma unroll
    for (int a=0;a<4;a++) for (int b=0;b<8;b++) for (int c=0;c<4;c++) acc[a][b][c]=0.f;

    load_stage1(sb,              tid, A,    FDIM, B,    FDIM);
    load_stage1(sb+STG1_BYTES,   tid, A+BK, FDIM, B+BK, FDIM);

    const int NC = FDIM/BK;   // 32
    #pragma unroll 1
    for (int c=0;c<NC;c++){
        if (c == NC-1) cpa_wait0(); else cpa_wait1();
        __syncthreads();
        if (c+2 < NC){
            int s2 = (c+2)%STAGES;
            int kc = (c+2)*BK;
            load_stage1(sb + s2*STG1_BYTES, tid, A+kc, FDIM, B+kc, FDIM);
        }
        compute_stage1(sb + (c%STAGES)*STG1_BYTES, acc, warp_m, warp_n, lane);
    }

    const int lane4 = lane>>2, lane2 = (lane&3)*2;
    __half* Sn = S + (size_t)node*B_SZ*HID;
    #pragma unroll
    for (int mt=0; mt<4; mt++){
        int r0 = m0 + warp_m + mt*16 + lane4;
        float lg0 = logits[(size_t)r0*NN + node];
        float lg1 = logits[(size_t)(r0+8)*NN + node];
        #pragma unroll
        for (int nt=0; nt<8; nt++){
            int h = warp_n + nt*8 + lane2;
            float fb0 = f2n_b[n0+h] + enc_b[h],   fb1 = f2n_b[n0+h+1] + enc_b[h+1];
            float ew0 = enc_w[h],                 ew1 = enc_w[h+1];
            float* a4 = acc[mt][nt];
            *(uint32_t*)(Sn + (size_t)r0*HID + h)     = pkh2(a4[0]+fb0+lg0*ew0, a4[1]+fb1+lg0*ew1);
            *(uint32_t*)(Sn + (size_t)(r0+8)*HID + h) = pkh2(a4[2]+fb0+lg1*ew0, a4[3]+fb1+lg1*ew1);
        }
    }
}

// ---------------- step GEMM (steps 1-3): tanh([S|SB] @ Wc^T + b2) -> O ----------------
__global__ void __launch_bounds__(256,1) step_mma(
    const __half* __restrict__ S, const __half* __restrict__ SB,
    __half* __restrict__ O)
{
    extern __shared__ char smraw[];
    uint32_t sb = (smem_u32(smraw) + 1023u) & ~1023u;
    const int tid = threadIdx.x, wid = tid>>5, lane = tid&31;
    const int m0 = blockIdx.x * BM;
    const int warp_m = (wid & 1) * 64;
    const int warp_n = (wid >> 1) * 64;

    float acc[4][8][4];
    #pragma unroll
    for (int a=0;a<4;a++) for (int b=0;b<8;b++) for (int c=0;c<4;c++) acc[a][b][c]=0.f;

    const __half* aS  = S  + (size_t)m0*HID;
    const __half* aSB = SB + (size_t)m0*HID;

    load_stage1(sb,              tid, aS,    HID, g_Wc16,    CATK);
    load_stage1(sb+STG1_BYTES,   tid, aS+BK, HID, g_Wc16+BK, CATK);

    const int NC = CATK/BK;   // 8
    #pragma unroll 1
    for (int c=0;c<NC;c++){
        if (c == NC-1) cpa_wait0(); else cpa_wait1();
        __syncthreads();
        if (c+2 < NC){
            int s2 = (c+2)%STAGES;
            int kg = (c+2)*BK;
            const __half* aP = (kg < HID ? aS : aSB) + (kg & (HID-1));
            load_stage1(sb + s2*STG1_BYTES, tid, aP, HID, g_Wc16+kg, CATK);
        }
        compute_stage1(sb + (c%STAGES)*STG1_BYTES, acc, warp_m, warp_n, lane);
    }

    const int lane4 = lane>>2, lane2 = (lane&3)*2;
    #pragma unroll
    for (int mt=0; mt<4; mt++){
        int r0 = m0 + warp_m + mt*16 + lane4;
        #pragma unroll
        for (int nt=0; nt<8; nt++){
            int cg = warp_n + nt*8 + lane2;
            float b0 = g_b2[cg], b1 = g_b2[cg+1];
            float* a4 = acc[mt][nt];
            *(uint32_t*)(O + (size_t)r0*HID + cg)     = pkh2(tanh_fast(a4[0]+b0), tanh_fast(a4[1]+b1));
            *(uint32_t*)(O + (size_t)(r0+8)*HID + cg) = pkh2(tanh_fast(a4[2]+b0), tanh_fast(a4[3]+b1));
        }
    }
}

// ---------------- step 4 fused: nodes 7/8 only, dot out_w, atomic out ----------------
__global__ void __launch_bounds__(256,1) step_out_mma(
    const __half* __restrict__ S, const __half* __restrict__ SB,
    const float* __restrict__ out_w, float* __restrict__ out)
{
    extern __shared__ char smraw[];
    uint32_t sb = (smem_u32(smraw) + 1023u) & ~1023u;
    __shared__ float sums[BM];
    const int tid = threadIdx.x, wid = tid>>5, lane = tid&31;
    const int m0 = 7*B_SZ + blockIdx.x * BM;
    const int warp_m = (wid & 1) * 64;
    const int warp_n = (wid >> 1) * 64;

    if (tid < BM) sums[tid] = 0.f;

    float acc[4][8][4];
    #pragma unroll
    for (int a=0;a<4;a++) for (int b=0;b<8;b++) for (int c=0;c<4;c++) acc[a][b][c]=0.f;

    const __half* aS  = S  + (size_t)m0*HID;
    const __half* aSB = SB + (size_t)m0*HID;

    load_stage1(sb,              tid, aS,    HID, g_Wc16,    CATK);
    load_stage1(sb+STG1_BYTES,   tid, aS+BK, HID, g_Wc16+BK, CATK);

    const int NC = CATK/BK;   // 8
    #pragma unroll 1
    for (int c=0;c<NC;c++){
        if (c == NC-1) cpa_wait0(); else cpa_wait1();
        __syncthreads();
        if (c+2 < NC){
            int s2 = (c+2)%STAGES;
            int kg = (c+2)*BK;
            const __half* aP = (kg < HID ? aS : aSB) + (kg & (HID-1));
            load_stage1(sb + s2*STG1_BYTES, tid, aP, HID, g_Wc16+kg, CATK);
        }
        compute_stage1(sb + (c%STAGES)*STG1_BYTES, acc, warp_m, warp_n, lane);
    }
    __syncthreads();

    const int lane4 = lane>>2, lane2 = (lane&3)*2;
    #pragma unroll
    for (int mt=0; mt<4; mt++){
        int lr0 = warp_m + mt*16 + lane4;
        float p0 = 0.f, p1 = 0.f;
        #pragma unroll
        for (int nt=0; nt<8; nt++){
            int cg = warp_n + nt*8 + lane2;
            float b0 = g_b2[cg], b1 = g_b2[cg+1];
            float w0 = out_w[cg], w1 = out_w[cg+1];
            float* a4 = acc[mt][nt];
            p0 += tanh_fast(a4[0]+b0)*w0 + tanh_fast(a4[1]+b1)*w1;
            p1 += tanh_fast(a4[2]+b0)*w0 + tanh_fast(a4[3]+b1)*w1;
        }
        atomicAdd(&sums[lr0], p0);
        atomicAdd(&sums[lr0+8], p1);
    }
    __syncthreads();
    if (tid < BM){
        int gr = m0 + tid;
        int node = gr >> 14;               // 7 or 8
        int b = gr & (B_SZ-1);
        atomicAdd(&out[(node-7)*B_SZ + b], sums[tid]);
    }
}

// ---------------- adjacency aggregate (node-major) ----------------
__global__ void sbar_kernel(const __half* __restrict__ S, __half* __restrict__ SB)
{
    int idx = blockIdx.x*blockDim.x + threadIdx.x;
    if (idx >= B_SZ*64) return;
    int b = idx>>6, c4 = (idx&63)<<2;
    float s[9][4];
    #pragma unroll
    for (int n=0;n<9;n++){
        uint2 v = *(const uint2*)(S + ((size_t)n*B_SZ + b)*HID + c4);
        float2 f01 = __half22float2(*(__half2*)&v.x);
        float2 f23 = __half22float2(*(__half2*)&v.y);
        s[n][0]=f01.x; s[n][1]=f01.y; s[n][2]=f23.x; s[n][3]=f23.y;
    }
    float o[9][4];
    #pragma unroll
    for (int e=0;e<4;e++){
        float tot = 0.f;
        #pragma unroll
        for (int n=0;n<9;n++) tot += s[n][e];
        float hub = s[0][e] + s[7][e] + s[8][e];
        float m78 = (tot - s[1][e]) * 0.125f;
        o[0][e] = tot * (1.f/9.f);
        o[1][e] = (s[0][e] + s[1][e]) * 0.5f;
        #pragma unroll
        for (int n=2;n<=6;n++) o[n][e] = (hub + s[n][e]) * 0.25f;
        o[7][e] = m78; o[8][e] = m78;
    }
    #pragma unroll
    for (int n=0;n<9;n++)
        *(uint2*)(SB + ((size_t)n*B_SZ + b)*HID + c4) =
            make_uint2(pkh2(o[n][0],o[n][1]), pkh2(o[n][2],o[n][3]));
}

__global__ void sbar78_kernel(const __half* __restrict__ S, __half* __restrict__ SB)
{
    int idx = blockIdx.x*blockDim.x + threadIdx.x;
    if (idx >= B_SZ*64) return;
    int b = idx>>6, c4 = (idx&63)<<2;
    float t0=0.f,t1=0.f,t2=0.f,t3=0.f, s10=0.f,s11=0.f,s12=0.f,s13=0.f;
    #pragma unroll
    for (int n=0;n<9;n++){
        uint2 v = *(const uint2*)(S + ((size_t)n*B_SZ + b)*HID + c4);
        float2 f01 = __half22float2(*(__half2*)&v.x);
        float2 f23 = __half22float2(*(__half2*)&v.y);
        t0+=f01.x; t1+=f01.y; t2+=f23.x; t3+=f23.y;
        if (n==1){ s10=f01.x; s11=f01.y; s12=f23.x; s13=f23.y; }
    }
    uint2 m = make_uint2(pkh2((t0-s10)*0.125f, (t1-s11)*0.125f),
                         pkh2((t2-s12)*0.125f, (t3-s13)*0.125f));
    *(uint2*)(SB + ((size_t)7*B_SZ + b)*HID + c4) = m;
    *(uint2*)(SB + ((size_t)8*B_SZ + b)*HID + c4) = m;
}

// ---------------- launch ----------------
extern "C" void kernel_launch(void* const* d_in, const int* in_sizes, int n_in,
                              void* d_out, int out_size)
{
    (void)in_sizes; (void)n_in; (void)out_size;
    const float* conc   = (const float*)d_in[0];
    const float* logits = (const float*)d_in[1];
    const float* enc_w  = (const float*)d_in[2];
    const float* enc_b  = (const float*)d_in[3];
    const float* f2n_w  = (const float*)d_in[4];
    const float* f2n_b  = (const float*)d_in[5];
    const float* msg_w  = (const float*)d_in[6];
    const float* msg_b  = (const float*)d_in[7];
    const float* upd_w  = (const float*)d_in[8];
    const float* upd_b  = (const float*)d_in[9];
    const float* out_w  = (const float*)d_in[10];
    const float* out_b  = (const float*)d_in[11];
    float* out = (float*)d_out;

    __half *a16,*b16,*s0,*s1,*sB;
    cudaGetSymbolAddress((void**)&a16, g_A16);
    cudaGetSymbolAddress((void**)&b16, g_B16);
    cudaGetSymbolAddress((void**)&s0,  g_S0);  cudaGetSymbolAddress((void**)&s1, g_S1);
    cudaGetSymbolAddress((void**)&sB,  g_SB);

    static int smem_set = 0;
    if (!smem_set){
        cudaFuncSetAttribute(gemm1_mma,    cudaFuncAttributeMaxDynamicSharedMemorySize, SMEM1_ALLOC);
        cudaFuncSetAttribute(step_mma,     cudaFuncAttributeMaxDynamicSharedMemorySize, SMEM1_ALLOC);
        cudaFuncSetAttribute(step_out_mma, cudaFuncAttributeMaxDynamicSharedMemorySize, SMEM1_ALLOC);
        smem_set = 1;
    }

    // 0) converts + prep + out init
    conv16_kernel<<<(B_SZ*FDIM/4)/256, 256>>>(conc, a16, B_SZ*FDIM/4);
    conv16_kernel<<<(SDIM*FDIM/4)/256, 256>>>(f2n_w, b16, SDIM*FDIM/4);
    prep_kernel<<<HID, HID>>>(msg_w, msg_b, upd_w, upd_b);
    init_out_kernel<<<(2*B_SZ)/256, 256>>>(out, out_b);

    // 1) big feature GEMM -> S0 (node-major), 1-product fp16
    {
        dim3 grid(NN, B_SZ/BM);   // (9, 128)
        gemm1_mma<<<grid, 256, SMEM1_ALLOC>>>(f2n_b, logits, enc_w, enc_b, s0);
    }

    // 2) steps 1-3 (ping-pong), 1-product fp16
    __half *cur = s0, *nxt = s1;
    for (int step = 0; step < 3; ++step){
        sbar_kernel<<<(B_SZ*64)/256, 256>>>(cur, sB);
        step_mma<<<MROWS/BM, 256, SMEM1_ALLOC>>>(cur, sB, nxt);
        __half* t = cur; cur = nxt; nxt = t;
    }

    // 3) step 4 fused with output head (nodes 7,8 only)
    sbar78_kernel<<<(B_SZ*64)/256, 256>>>(cur, sB);
    step_out_mma<<<2*B_SZ/BM, 256, SMEM1_ALLOC>>>(cur, sB, out_w, out);
}

// round 10
// speedup vs baseline: 6.6824x; 1.0047x over previous
#include <cuda_runtime.h>
#include <cuda_fp16.h>
#include <stdint.h>
#include <math.h>

#define B_SZ   16384
#define FDIM   2048
#define HID    256
#define NN     9
#define SDIM   (NN*HID)        // 2304
#define CATK   (2*HID)         // 512
#define MROWS  (B_SZ*NN)       // 147456

#define BM 128
#define BN1 256
#define BK 64
#define STAGES 4
#define OFF_B1 16384
#define STG1_BYTES (48*1024)    // A 16KB + B 32KB
#define SMEM1_ALLOC (STAGES*STG1_BYTES + 1024)

// ---------------- device scratch (no allocation allowed) ----------------
// States NODE-MAJOR: S[node*B_SZ + b][h]
__device__ __half g_A16[(size_t)B_SZ*FDIM];
__device__ __half g_B16[(size_t)SDIM*FDIM];
__device__ __half g_S0[(size_t)MROWS*HID];
__device__ __half g_S1[(size_t)MROWS*HID];
__device__ __half g_SB[(size_t)MROWS*HID];
__device__ __half g_Wc16[HID*CATK];
__device__ float g_b2[HID];

// ---------------- helpers ----------------
__device__ __forceinline__ uint32_t smem_u32(const void* p){
    uint32_t a;
    asm("{ .reg .u64 t; cvta.to.shared.u64 t, %1; cvt.u32.u64 %0, t; }" : "=r"(a) : "l"(p));
    return a;
}
__device__ __forceinline__ void cpa16(uint32_t dst, const void* src){
    asm volatile("cp.async.cg.shared.global [%0], [%1], 16;" :: "r"(dst), "l"(src) : "memory");
}
__device__ __forceinline__ void cpa_commit(){ asm volatile("cp.async.commit_group;" ::: "memory"); }
__device__ __forceinline__ void cpa_wait2(){ asm volatile("cp.async.wait_group 2;" ::: "memory"); }
__device__ __forceinline__ void cpa_wait1(){ asm volatile("cp.async.wait_group 1;" ::: "memory"); }
__device__ __forceinline__ void cpa_wait0(){ asm volatile("cp.async.wait_group 0;" ::: "memory"); }

__device__ __forceinline__ void ldm4(uint32_t addr, uint32_t* r){
    asm volatile("ldmatrix.sync.aligned.m8n8.x4.shared.b16 {%0,%1,%2,%3}, [%4];"
        : "=r"(r[0]),"=r"(r[1]),"=r"(r[2]),"=r"(r[3]) : "r"(addr));
}
__device__ __forceinline__ void mma16816(float* d, const uint32_t* a, uint32_t b0, uint32_t b1){
    asm volatile("mma.sync.aligned.m16n8k16.row.col.f32.f16.f16.f32 "
        "{%0,%1,%2,%3}, {%4,%5,%6,%7}, {%8,%9}, {%0,%1,%2,%3};"
        : "+f"(d[0]),"+f"(d[1]),"+f"(d[2]),"+f"(d[3])
        : "r"(a[0]),"r"(a[1]),"r"(a[2]),"r"(a[3]), "r"(b0),"r"(b1));
}

__device__ __forceinline__ uint32_t a_addr(uint32_t base, int row0, int c0, int lane){
    int r = row0 + (lane & 7) + ((lane >> 3) & 1) * 8;
    int c = c0 + (lane >> 4);
    return base + r*128 + ((c ^ (r & 7)) << 4);
}
__device__ __forceinline__ uint32_t b_addr(uint32_t base, int n0, int c0, int lane){
    int r = n0 + (lane & 7) + (lane >> 4) * 8;
    int c = c0 + ((lane >> 3) & 1);
    return base + r*128 + ((c ^ (r & 7)) << 4);
}

__device__ __forceinline__ uint32_t pkh2(float a, float b){
    __half2 h = __floats2half2_rn(a, b);
    return *(uint32_t*)&h;
}
__device__ __forceinline__ float tanh_fast(float x){
    float ax = fabsf(x);
    float z = __expf(-2.f*ax);
    float y = __fdividef(1.f - z, 1.f + z);
    return copysignf(y, x);
}

// ======== tile machinery (1-product, 128x256 CTA tile) ========
__device__ __forceinline__ void load_stage1(uint32_t base, int tid,
    const __half* aP, int lda, const __half* bP, int ldb)
{
    #pragma unroll
    for (int i=0;i<4;i++){
        int id = i*256 + tid;
        int row = id>>3, c = id&7;
        cpa16(base + row*128 + ((c ^ (row&7))<<4), aP + (size_t)row*lda + (c<<3));
    }
    #pragma unroll
    for (int i=0;i<8;i++){
        int id = i*256 + tid;
        int row = id>>3, c = id&7;
        cpa16(base + OFF_B1 + row*128 + ((c ^ (row&7))<<4), bP + (size_t)row*ldb + (c<<3));
    }
    cpa_commit();
}

__device__ __forceinline__ void ld_frags(uint32_t base, int c0, int warp_m, int warp_n,
                                         int lane, uint32_t aF[4][4], uint32_t bF[4][4])
{
    #pragma unroll
    for (int mt=0; mt<4; mt++)
        ldm4(a_addr(base, warp_m + mt*16, c0, lane), aF[mt]);
    #pragma unroll
    for (int g=0; g<4; g++)
        ldm4(b_addr(base + OFF_B1, warp_n + g*16, c0, lane), bF[g]);
}
__device__ __forceinline__ void do_mmas(float acc[4][8][4], uint32_t aF[4][4], uint32_t bF[4][4])
{
    #pragma unroll
    for (int mt=0; mt<4; mt++)
        #pragma unroll
        for (int nt=0; nt<8; nt++){
            int g = nt>>1, p = (nt&1)*2;
            mma16816(acc[mt][nt], aF[mt], bF[g][p], bF[g][p+1]);
        }
}

// register-double-buffered compute over one 64-K chunk
__device__ __forceinline__ void compute_stage1(uint32_t base, float acc[4][8][4],
                                               int warp_m, int warp_n, int lane)
{
    uint32_t aF[2][4][4], bF[2][4][4];
    ld_frags(base, 0, warp_m, warp_n, lane, aF[0], bF[0]);
    #pragma unroll
    for (int k16=0; k16<4; k16++){
        if (k16 < 3)
            ld_frags(base, 2*(k16+1), warp_m, warp_n, lane, aF[(k16+1)&1], bF[(k16+1)&1]);
        do_mmas(acc, aF[k16&1], bF[k16&1]);
    }
}

// pipeline wait helper: allow up to min(NC-1-c, 2) groups in flight
__device__ __forceinline__ void pipe_wait(int c, int NC){
    int rem = NC - 1 - c;
    if (rem >= 2) cpa_wait2();
    else if (rem == 1) cpa_wait1();
    else cpa_wait0();
}

// ---------------- converts / prep ----------------
__global__ void conv16_kernel(const float* __restrict__ x, __half* __restrict__ h, int n4)
{
    int i = blockIdx.x*blockDim.x + threadIdx.x;
    if (i >= n4) return;
    float4 v = ((const float4*)x)[i];
    ((uint2*)h)[i] = make_uint2(pkh2(v.x,v.y), pkh2(v.z,v.w));
}
__global__ void prep_kernel(const float* __restrict__ msg_w, const float* __restrict__ msg_b,
                            const float* __restrict__ upd_w, const float* __restrict__ upd_b)
{
    int o = blockIdx.x, k = threadIdx.x;
    const float* u2 = upd_w + o*CATK + HID;
    g_Wc16[o*CATK + k] = __float2half_rn(upd_w[o*CATK + k]);
    float acc = 0.f;
    #pragma unroll 4
    for (int m=0;m<HID;m++) acc += u2[m]*msg_w[m*HID + k];
    g_Wc16[o*CATK + HID + k] = __float2half_rn(acc);
    if (k==0){
        float bb = upd_b[o];
        for (int m=0;m<HID;m++) bb += u2[m]*msg_b[m];
        g_b2[o] = bb;
    }
}

// ---------------- GEMM1: conc @ f2n_w^T + biases + encoder -> S (node-major) ----------------
__global__ void __launch_bounds__(256,1) gemm1_mma(
    const float* __restrict__ f2n_b, const float* __restrict__ logits,
    const float* __restrict__ enc_w, const float* __restrict__ enc_b,
    __half* __restrict__ S)
{
    extern __shared__ char smraw[];
    uint32_t sb = (smem_u32(smraw) + 1023u) & ~1023u;
    const int tid = threadIdx.x, wid = tid>>5, lane = tid&31;
    const int node = blockIdx.x;
    const int n0 = node * BN1;
    const int m0 = blockIdx.y * BM;
    const int warp_m = (wid & 1) * 64;
    const int warp_n = (wid >> 1) * 64;

    const __half* A = g_A16 + (size_t)m0*FDIM;
    const __half* B = g_B16 + (size_t)n0*FDIM;

    float acc[4][8][4];
    #pragma unroll
    for (int a=0;a<4;a++) for (int b=0;b<8;b++) for (int c=0;c<4;c++) acc[a][b][c]=0.f;

    load_stage1(sb,               tid, A,      FDIM, B,      FDIM);
    load_stage1(sb+STG1_BYTES,    tid, A+BK,   FDIM, B+BK,   FDIM);
    load_stage1(sb+2*STG1_BYTES,  tid, A+2*BK, FDIM, B+2*BK, FDIM);

    const int NC = FDIM/BK;   // 32
    #pragma unroll 1
    for (int c=0;c<NC;c++){
        pipe_wait(c, NC);
        __syncthreads();
        if (c+3 < NC){
            int s2 = (c+3)%STAGES;
            int kc = (c+3)*BK;
            load_stage1(sb + s2*STG1_BYTES, tid, A+kc, FDIM, B+kc, FDIM);
        }
        compute_stage1(sb + (c%STAGES)*STG1_BYTES, acc, warp_m, warp_n, lane);
    }

    const int lane4 = lane>>2, lane2 = (lane&3)*2;
    __half* Sn = S + (size_t)node*B_SZ*HID;
    #pragma unroll
    for (int mt=0; mt<4; mt++){
        int r0 = m0 + warp_m + mt*16 + lane4;
        float lg0 = logits[(size_t)r0*NN + node];
        float lg1 = logits[(size_t)(r0+8)*NN + node];
        #pragma unroll
        for (int nt=0; nt<8; nt++){
            int h = warp_n + nt*8 + lane2;
            float fb0 = f2n_b[n0+h] + enc_b[h],   fb1 = f2n_b[n0+h+1] + enc_b[h+1];
            float ew0 = enc_w[h],                 ew1 = enc_w[h+1];
            float* a4 = acc[mt][nt];
            *(uint32_t*)(Sn + (size_t)r0*HID + h)     = pkh2(a4[0]+fb0+lg0*ew0, a4[1]+fb1+lg0*ew1);
            *(uint32_t*)(Sn + (size_t)(r0+8)*HID + h) = pkh2(a4[2]+fb0+lg1*ew0, a4[3]+fb1+lg1*ew1);
        }
    }
}

// ---------------- step GEMM (steps 1-3): tanh([S|SB] @ Wc^T + b2) -> O ----------------
__global__ void __launch_bounds__(256,1) step_mma(
    const __half* __restrict__ S, const __half* __restrict__ SB,
    __half* __restrict__ O)
{
    extern __shared__ char smraw[];
    uint32_t sb = (smem_u32(smraw) + 1023u) & ~1023u;
    const int tid = threadIdx.x, wid = tid>>5, lane = tid&31;
    const int m0 = blockIdx.x * BM;
    const int warp_m = (wid & 1) * 64;
    const int warp_n = (wid >> 1) * 64;

    float acc[4][8][4];
    #pragma unroll
    for (int a=0;a<4;a++) for (int b=0;b<8;b++) for (int c=0;c<4;c++) acc[a][b][c]=0.f;

    const __half* aS  = S  + (size_t)m0*HID;
    const __half* aSB = SB + (size_t)m0*HID;

    load_stage1(sb,               tid, aS,      HID, g_Wc16,      CATK);
    load_stage1(sb+STG1_BYTES,    tid, aS+BK,   HID, g_Wc16+BK,   CATK);
    load_stage1(sb+2*STG1_BYTES,  tid, aS+2*BK, HID, g_Wc16+2*BK, CATK);

    const int NC = CATK/BK;   // 8
    #pragma unroll 1
    for (int c=0;c<NC;c++){
        pipe_wait(c, NC);
        __syncthreads();
        if (c+3 < NC){
            int s2 = (c+3)%STAGES;
            int kg = (c+3)*BK;
            const __half* aP = (kg < HID ? aS : aSB) + (kg & (HID-1));
            load_stage1(sb + s2*STG1_BYTES, tid, aP, HID, g_Wc16+kg, CATK);
        }
        compute_stage1(sb + (c%STAGES)*STG1_BYTES, acc, warp_m, warp_n, lane);
    }

    const int lane4 = lane>>2, lane2 = (lane&3)*2;
    #pragma unroll
    for (int mt=0; mt<4; mt++){
        int r0 = m0 + warp_m + mt*16 + lane4;
        #pragma unroll
        for (int nt=0; nt<8; nt++){
            int cg = warp_n + nt*8 + lane2;
            float b0 = g_b2[cg], b1 = g_b2[cg+1];
            float* a4 = acc[mt][nt];
            *(uint32_t*)(O + (size_t)r0*HID + cg)     = pkh2(tanh_fast(a4[0]+b0), tanh_fast(a4[1]+b1));
            *(uint32_t*)(O + (size_t)(r0+8)*HID + cg) = pkh2(tanh_fast(a4[2]+b0), tanh_fast(a4[3]+b1));
        }
    }
}

// ---------------- step 4 fused: nodes 7/8 only, dot out_w, direct store ----------------
__global__ void __launch_bounds__(256,1) step_out_mma(
    const __half* __restrict__ S, const __half* __restrict__ SB,
    const float* __restrict__ out_w, const float* __restrict__ out_b,
    float* __restrict__ out)
{
    extern __shared__ char smraw[];
    uint32_t sb = (smem_u32(smraw) + 1023u) & ~1023u;
    __shared__ float sums[BM];
    const int tid = threadIdx.x, wid = tid>>5, lane = tid&31;
    const int m0 = 7*B_SZ + blockIdx.x * BM;
    const int warp_m = (wid & 1) * 64;
    const int warp_n = (wid >> 1) * 64;

    if (tid < BM) sums[tid] = 0.f;

    float acc[4][8][4];
    #pragma unroll
    for (int a=0;a<4;a++) for (int b=0;b<8;b++) for (int c=0;c<4;c++) acc[a][b][c]=0.f;

    const __half* aS  = S  + (size_t)m0*HID;
    const __half* aSB = SB + (size_t)m0*HID;

    load_stage1(sb,               tid, aS,      HID, g_Wc16,      CATK);
    load_stage1(sb+STG1_BYTES,    tid, aS+BK,   HID, g_Wc16+BK,   CATK);
    load_stage1(sb+2*STG1_BYTES,  tid, aS+2*BK, HID, g_Wc16+2*BK, CATK);

    const int NC = CATK/BK;   // 8
    #pragma unroll 1
    for (int c=0;c<NC;c++){
        pipe_wait(c, NC);
        __syncthreads();
        if (c+3 < NC){
            int s2 = (c+3)%STAGES;
            int kg = (c+3)*BK;
            const __half* aP = (kg < HID ? aS : aSB) + (kg & (HID-1));
            load_stage1(sb + s2*STG1_BYTES, tid, aP, HID, g_Wc16+kg, CATK);
        }
        compute_stage1(sb + (c%STAGES)*STG1_BYTES, acc, warp_m, warp_n, lane);
    }
    __syncthreads();

    const int lane4 = lane>>2, lane2 = (lane&3)*2;
    #pragma unroll
    for (int mt=0; mt<4; mt++){
        int lr0 = warp_m + mt*16 + lane4;
        float p0 = 0.f, p1 = 0.f;
        #pragma unroll
        for (int nt=0; nt<8; nt++){
            int cg = warp_n + nt*8 + lane2;
            float b0 = g_b2[cg], b1 = g_b2[cg+1];
            float w0 = out_w[cg], w1 = out_w[cg+1];
            float* a4 = acc[mt][nt];
            p0 += tanh_fast(a4[0]+b0)*w0 + tanh_fast(a4[1]+b1)*w1;
            p1 += tanh_fast(a4[2]+b0)*w0 + tanh_fast(a4[3]+b1)*w1;
        }
        atomicAdd(&sums[lr0], p0);
        atomicAdd(&sums[lr0+8], p1);
    }
    __syncthreads();
    if (tid < BM){
        int gr = m0 + tid;
        int node = gr >> 14;               // 7 or 8
        int b = gr & (B_SZ-1);
        out[(node-7)*B_SZ + b] = sums[tid] + out_b[0];
    }
}

// ---------------- adjacency aggregate (node-major, uint4) ----------------
__global__ void sbar_kernel(const __half* __restrict__ S, __half* __restrict__ SB)
{
    int idx = blockIdx.x*blockDim.x + threadIdx.x;
    if (idx >= B_SZ*32) return;
    int b = idx>>5, c8 = (idx&31)<<3;
    float s[9][8];
    #pragma unroll
    for (int n=0;n<9;n++){
        uint4 v = *(const uint4*)(S + ((size_t)n*B_SZ + b)*HID + c8);
        float2 f0 = __half22float2(*(__half2*)&v.x);
        float2 f1 = __half22float2(*(__half2*)&v.y);
        float2 f2 = __half22float2(*(__half2*)&v.z);
        float2 f3 = __half22float2(*(__half2*)&v.w);
        s[n][0]=f0.x; s[n][1]=f0.y; s[n][2]=f1.x; s[n][3]=f1.y;
        s[n][4]=f2.x; s[n][5]=f2.y; s[n][6]=f3.x; s[n][7]=f3.y;
    }
    float o[9][8];
    #pragma unroll
    for (int e=0;e<8;e++){
        float tot = 0.f;
        #pragma unroll
        for (int n=0;n<9;n++) tot += s[n][e];
        float hub = s[0][e] + s[7][e] + s[8][e];
        float m78 = (tot - s[1][e]) * 0.125f;
        o[0][e] = tot * (1.f/9.f);
        o[1][e] = (s[0][e] + s[1][e]) * 0.5f;
        #pragma unroll
        for (int n=2;n<=6;n++) o[n][e] = (hub + s[n][e]) * 0.25f;
        o[7][e] = m78; o[8][e] = m78;
    }
    #pragma unroll
    for (int n=0;n<9;n++){
        uint4 w;
        w.x = pkh2(o[n][0],o[n][1]); w.y = pkh2(o[n][2],o[n][3]);
        w.z = pkh2(o[n][4],o[n][5]); w.w = pkh2(o[n][6],o[n][7]);
        *(uint4*)(SB + ((size_t)n*B_SZ + b)*HID + c8) = w;
    }
}

__global__ void sbar78_kernel(const __half* __restrict__ S, __half* __restrict__ SB)
{
    int idx = blockIdx.x*blockDim.x + threadIdx.x;
    if (idx >= B_SZ*32) return;
    int b = idx>>5, c8 = (idx&31)<<3;
    float t[8] = {0,0,0,0,0,0,0,0}, s1[8];
    #pragma unroll
    for (int n=0;n<9;n++){
        uint4 v = *(const uint4*)(S + ((size_t)n*B_SZ + b)*HID + c8);
        float2 f0 = __half22float2(*(__half2*)&v.x);
        float2 f1 = __half22float2(*(__half2*)&v.y);
        float2 f2 = __half22float2(*(__half2*)&v.z);
        float2 f3 = __half22float2(*(__half2*)&v.w);
        float e[8] = {f0.x,f0.y,f1.x,f1.y,f2.x,f2.y,f3.x,f3.y};
        #pragma unroll
        for (int q=0;q<8;q++) t[q] += e[q];
        if (n==1){
            #pragma unroll
            for (int q=0;q<8;q++) s1[q] = e[q];
        }
    }
    uint4 m;
    m.x = pkh2((t[0]-s1[0])*0.125f, (t[1]-s1[1])*0.125f);
    m.y = pkh2((t[2]-s1[2])*0.125f, (t[3]-s1[3])*0.125f);
    m.z = pkh2((t[4]-s1[4])*0.125f, (t[5]-s1[5])*0.125f);
    m.w = pkh2((t[6]-s1[6])*0.125f, (t[7]-s1[7])*0.125f);
    *(uint4*)(SB + ((size_t)7*B_SZ + b)*HID + c8) = m;
    *(uint4*)(SB + ((size_t)8*B_SZ + b)*HID + c8) = m;
}

// ---------------- launch ----------------
extern "C" void kernel_launch(void* const* d_in, const int* in_sizes, int n_in,
                              void* d_out, int out_size)
{
    (void)in_sizes; (void)n_in; (void)out_size;
    const float* conc   = (const float*)d_in[0];
    const float* logits = (const float*)d_in[1];
    const float* enc_w  = (const float*)d_in[2];
    const float* enc_b  = (const float*)d_in[3];
    const float* f2n_w  = (const float*)d_in[4];
    const float* f2n_b  = (const float*)d_in[5];
    const float* msg_w  = (const float*)d_in[6];
    const float* msg_b  = (const float*)d_in[7];
    const float* upd_w  = (const float*)d_in[8];
    const float* upd_b  = (const float*)d_in[9];
    const float* out_w  = (const float*)d_in[10];
    const float* out_b  = (const float*)d_in[11];
    float* out = (float*)d_out;

    __half *a16,*b16,*s0,*s1,*sB;
    cudaGetSymbolAddress((void**)&a16, g_A16);
    cudaGetSymbolAddress((void**)&b16, g_B16);
    cudaGetSymbolAddress((void**)&s0,  g_S0);  cudaGetSymbolAddress((void**)&s1, g_S1);
    cudaGetSymbolAddress((void**)&sB,  g_SB);

    static int smem_set = 0;
    if (!smem_set){
        cudaFuncSetAttribute(gemm1_mma,    cudaFuncAttributeMaxDynamicSharedMemorySize, SMEM1_ALLOC);
        cudaFuncSetAttribute(step_mma,     cudaFuncAttributeMaxDynamicSharedMemorySize, SMEM1_ALLOC);
        cudaFuncSetAttribute(step_out_mma, cudaFuncAttributeMaxDynamicSharedMemorySize, SMEM1_ALLOC);
        smem_set = 1;
    }

    // 0) converts + prep
    conv16_kernel<<<(B_SZ*FDIM/4)/256, 256>>>(conc, a16, B_SZ*FDIM/4);
    conv16_kernel<<<(SDIM*FDIM/4)/256, 256>>>(f2n_w, b16, SDIM*FDIM/4);
    prep_kernel<<<HID, HID>>>(msg_w, msg_b, upd_w, upd_b);

    // 1) big feature GEMM -> S0 (node-major), 1-product fp16
    {
        dim3 grid(NN, B_SZ/BM);   // (9, 128)
        gemm1_mma<<<grid, 256, SMEM1_ALLOC>>>(f2n_b, logits, enc_w, enc_b, s0);
    }

    // 2) steps 1-3 (ping-pong), 1-product fp16
    __half *cur = s0, *nxt = s1;
    for (int step = 0; step < 3; ++step){
        sbar_kernel<<<(B_SZ*32)/256, 256>>>(cur, sB);
        step_mma<<<MROWS/BM, 256, SMEM1_ALLOC>>>(cur, sB, nxt);
        __half* t = cur; cur = nxt; nxt = t;
    }

    // 3) step 4 fused with output head (nodes 7,8 only)
    sbar78_kernel<<<(B_SZ*32)/256, 256>>>(cur, sB);
    step_out_mma<<<2*B_SZ/BM, 256, SMEM1_ALLOC>>>(cur, sB, out_w, out_b, out);
}

// round 11
// speedup vs baseline: 6.7073x; 1.0037x over previous
#include <cuda_runtime.h>
#include <cuda_fp16.h>
#include <stdint.h>
#include <math.h>

#define B_SZ   16384
#define FDIM   2048
#define HID    256
#define NN     9
#define SDIM   (NN*HID)        // 2304
#define CATK   (2*HID)         // 512
#define MROWS  (B_SZ*NN)       // 147456

#define BM 128
#define BN1 256
#define BK 64
#define STAGES 4
#define OFF_B1 16384
#define STG1_BYTES (48*1024)    // A 16KB + B 32KB
#define SMEM1_ALLOC (STAGES*STG1_BYTES + 1024)

// ---------------- device scratch (no allocation allowed) ----------------
// States NODE-MAJOR: S[node*B_SZ + b][h]
__device__ __half g_A16[(size_t)B_SZ*FDIM];
__device__ __half g_B16[(size_t)SDIM*FDIM];
__device__ __half g_S0[(size_t)MROWS*HID];
__device__ __half g_S1[(size_t)MROWS*HID];
__device__ __half g_SB[(size_t)MROWS*HID];
__device__ __half g_Wc16[HID*CATK];
__device__ float g_b2[HID];

// ---------------- helpers ----------------
__device__ __forceinline__ uint32_t smem_u32(const void* p){
    uint32_t a;
    asm("{ .reg .u64 t; cvta.to.shared.u64 t, %1; cvt.u32.u64 %0, t; }" : "=r"(a) : "l"(p));
    return a;
}
__device__ __forceinline__ void cpa16(uint32_t dst, const void* src){
    asm volatile("cp.async.cg.shared.global [%0], [%1], 16;" :: "r"(dst), "l"(src) : "memory");
}
__device__ __forceinline__ void cpa_commit(){ asm volatile("cp.async.commit_group;" ::: "memory"); }
__device__ __forceinline__ void cpa_wait2(){ asm volatile("cp.async.wait_group 2;" ::: "memory"); }
__device__ __forceinline__ void cpa_wait1(){ asm volatile("cp.async.wait_group 1;" ::: "memory"); }
__device__ __forceinline__ void cpa_wait0(){ asm volatile("cp.async.wait_group 0;" ::: "memory"); }

__device__ __forceinline__ void ldm4(uint32_t addr, uint32_t* r){
    asm volatile("ldmatrix.sync.aligned.m8n8.x4.shared.b16 {%0,%1,%2,%3}, [%4];"
        : "=r"(r[0]),"=r"(r[1]),"=r"(r[2]),"=r"(r[3]) : "r"(addr));
}
__device__ __forceinline__ void mma16816(float* d, const uint32_t* a, uint32_t b0, uint32_t b1){
    asm volatile("mma.sync.aligned.m16n8k16.row.col.f32.f16.f16.f32 "
        "{%0,%1,%2,%3}, {%4,%5,%6,%7}, {%8,%9}, {%0,%1,%2,%3};"
        : "+f"(d[0]),"+f"(d[1]),"+f"(d[2]),"+f"(d[3])
        : "r"(a[0]),"r"(a[1]),"r"(a[2]),"r"(a[3]), "r"(b0),"r"(b1));
}

__device__ __forceinline__ uint32_t a_addr(uint32_t base, int row0, int c0, int lane){
    int r = row0 + (lane & 7) + ((lane >> 3) & 1) * 8;
    int c = c0 + (lane >> 4);
    return base + r*128 + ((c ^ (r & 7)) << 4);
}
__device__ __forceinline__ uint32_t b_addr(uint32_t base, int n0, int c0, int lane){
    int r = n0 + (lane & 7) + (lane >> 4) * 8;
    int c = c0 + ((lane >> 3) & 1);
    return base + r*128 + ((c ^ (r & 7)) << 4);
}

__device__ __forceinline__ uint32_t pkh2(float a, float b){
    __half2 h = __floats2half2_rn(a, b);
    return *(uint32_t*)&h;
}
__device__ __forceinline__ float tanh_fast(float x){
    float ax = fabsf(x);
    float z = __expf(-2.f*ax);
    float y = __fdividef(1.f - z, 1.f + z);
    return copysignf(y, x);
}

// ======== tile machinery (1-product, 128x256 CTA tile) ========
__device__ __forceinline__ void load_stage1(uint32_t base, int tid,
    const __half* aP, int lda, const __half* bP, int ldb)
{
    #pragma unroll
    for (int i=0;i<4;i++){
        int id = i*256 + tid;
        int row = id>>3, c = id&7;
        cpa16(base + row*128 + ((c ^ (row&7))<<4), aP + (size_t)row*lda + (c<<3));
    }
    #pragma unroll
    for (int i=0;i<8;i++){
        int id = i*256 + tid;
        int row = id>>3, c = id&7;
        cpa16(base + OFF_B1 + row*128 + ((c ^ (row&7))<<4), bP + (size_t)row*ldb + (c<<3));
    }
    cpa_commit();
}

// single-buffered compute over one 64-K chunk (R8-proven: lowest reg pressure)
__device__ __forceinline__ void compute_stage1(uint32_t base, float acc[4][8][4],
                                               int warp_m, int warp_n, int lane)
{
    #pragma unroll
    for (int k16=0; k16<4; k16++){
        int c0 = 2*k16;
        uint32_t aF[4][4], bF[4][4];
        #pragma unroll
        for (int mt=0; mt<4; mt++)
            ldm4(a_addr(base, warp_m + mt*16, c0, lane), aF[mt]);
        #pragma unroll
        for (int g=0; g<4; g++)
            ldm4(b_addr(base + OFF_B1, warp_n + g*16, c0, lane), bF[g]);
        #pragma unroll
        for (int mt=0; mt<4; mt++)
            #pragma unroll
            for (int nt=0; nt<8; nt++){
                int g = nt>>1, p = (nt&1)*2;
                mma16816(acc[mt][nt], aF[mt], bF[g][p], bF[g][p+1]);
            }
    }
}

// pipeline wait helper: allow up to min(NC-1-c, 2) groups in flight
__device__ __forceinline__ void pipe_wait(int c, int NC){
    int rem = NC - 1 - c;
    if (rem >= 2) cpa_wait2();
    else if (rem == 1) cpa_wait1();
    else cpa_wait0();
}

// ---------------- converts / prep ----------------
__global__ void conv16_kernel(const float* __restrict__ x, __half* __restrict__ h, int n4)
{
    int i = blockIdx.x*blockDim.x + threadIdx.x;
    if (i >= n4) return;
    float4 v = ((const float4*)x)[i];
    ((uint2*)h)[i] = make_uint2(pkh2(v.x,v.y), pkh2(v.z,v.w));
}
__global__ void prep_kernel(const float* __restrict__ msg_w, const float* __restrict__ msg_b,
                            const float* __restrict__ upd_w, const float* __restrict__ upd_b)
{
    int o = blockIdx.x, k = threadIdx.x;
    const float* u2 = upd_w + o*CATK + HID;
    g_Wc16[o*CATK + k] = __float2half_rn(upd_w[o*CATK + k]);
    float acc = 0.f;
    #pragma unroll 4
    for (int m=0;m<HID;m++) acc += u2[m]*msg_w[m*HID + k];
    g_Wc16[o*CATK + HID + k] = __float2half_rn(acc);
    if (k==0){
        float bb = upd_b[o];
        for (int m=0;m<HID;m++) bb += u2[m]*msg_b[m];
        g_b2[o] = bb;
    }
}

// ---------------- GEMM1: conc @ f2n_w^T + biases + encoder -> S (node-major) ----------------
__global__ void __launch_bounds__(256,1) gemm1_mma(
    const float* __restrict__ f2n_b, const float* __restrict__ logits,
    const float* __restrict__ enc_w, const float* __restrict__ enc_b,
    __half* __restrict__ S)
{
    extern __shared__ char smraw[];
    uint32_t sb = (smem_u32(smraw) + 1023u) & ~1023u;
    const int tid = threadIdx.x, wid = tid>>5, lane = tid&31;
    const int node = blockIdx.x;
    const int n0 = node * BN1;
    const int m0 = blockIdx.y * BM;
    const int warp_m = (wid & 1) * 64;
    const int warp_n = (wid >> 1) * 64;

    const __half* A = g_A16 + (size_t)m0*FDIM;
    const __half* B = g_B16 + (size_t)n0*FDIM;

    float acc[4][8][4];
    #pragma unroll
    for (int a=0;a<4;a++) for (int b=0;b<8;b++) for (int c=0;c<4;c++) acc[a][b][c]=0.f;

    load_stage1(sb,               tid, A,      FDIM, B,      FDIM);
    load_stage1(sb+STG1_BYTES,    tid, A+BK,   FDIM, B+BK,   FDIM);
    load_stage1(sb+2*STG1_BYTES,  tid, A+2*BK, FDIM, B+2*BK, FDIM);

    const int NC = FDIM/BK;   // 32
    #pragma unroll 1
    for (int c=0;c<NC;c++){
        pipe_wait(c, NC);
        __syncthreads();
        if (c+3 < NC){
            int s2 = (c+3)%STAGES;
            int kc = (c+3)*BK;
            load_stage1(sb + s2*STG1_BYTES, tid, A+kc, FDIM, B+kc, FDIM);
        }
        compute_stage1(sb + (c%STAGES)*STG1_BYTES, acc, warp_m, warp_n, lane);
    }

    const int lane4 = lane>>2, lane2 = (lane&3)*2;
    __half* Sn = S + (size_t)node*B_SZ*HID;
    #pragma unroll
    for (int mt=0; mt<4; mt++){
        int r0 = m0 + warp_m + mt*16 + lane4;
        float lg0 = logits[(size_t)r0*NN + node];
        float lg1 = logits[(size_t)(r0+8)*NN + node];
        #pragma unroll
        for (int nt=0; nt<8; nt++){
            int h = warp_n + nt*8 + lane2;
            float fb0 = f2n_b[n0+h] + enc_b[h],   fb1 = f2n_b[n0+h+1] + enc_b[h+1];
            float ew0 = enc_w[h],                 ew1 = enc_w[h+1];
            float* a4 = acc[mt][nt];
            *(uint32_t*)(Sn + (size_t)r0*HID + h)     = pkh2(a4[0]+fb0+lg0*ew0, a4[1]+fb1+lg0*ew1);
            *(uint32_t*)(Sn + (size_t)(r0+8)*HID + h) = pkh2(a4[2]+fb0+lg1*ew0, a4[3]+fb1+lg1*ew1);
        }
    }
}

// ---------------- step GEMM (steps 1-3): tanh([S|SB] @ Wc^T + b2) -> O ----------------
__global__ void __launch_bounds__(256,1) step_mma(
    const __half* __restrict__ S, const __half* __restrict__ SB,
    __half* __restrict__ O)
{
    extern __shared__ char smraw[];
    uint32_t sb = (smem_u32(smraw) + 1023u) & ~1023u;
    const int tid = threadIdx.x, wid = tid>>5, lane = tid&31;
    const int m0 = blockIdx.x * BM;
    const int warp_m = (wid & 1) * 64;
    const int warp_n = (wid >> 1) * 64;

    float acc[4][8][4];
    #pragma unroll
    for (int a=0;a<4;a++) for (int b=0;b<8;b++) for (int c=0;c<4;c++) acc[a][b][c]=0.f;

    const __half* aS  = S  + (size_t)m0*HID;
    const __half* aSB = SB + (size_t)m0*HID;

    load_stage1(sb,               tid, aS,      HID, g_Wc16,      CATK);
    load_stage1(sb+STG1_BYTES,    tid, aS+BK,   HID, g_Wc16+BK,   CATK);
    load_stage1(sb+2*STG1_BYTES,  tid, aS+2*BK, HID, g_Wc16+2*BK, CATK);

    const int NC = CATK/BK;   // 8
    #pragma unroll 1
    for (int c=0;c<NC;c++){
        pipe_wait(c, NC);
        __syncthreads();
        if (c+3 < NC){
            int s2 = (c+3)%STAGES;
            int kg = (c+3)*BK;
            const __half* aP = (kg < HID ? aS : aSB) + (kg & (HID-1));
            load_stage1(sb + s2*STG1_BYTES, tid, aP, HID, g_Wc16+kg, CATK);
        }
        compute_stage1(sb + (c%STAGES)*STG1_BYTES, acc, warp_m, warp_n, lane);
    }

    const int lane4 = lane>>2, lane2 = (lane&3)*2;
    #pragma unroll
    for (int mt=0; mt<4; mt++){
        int r0 = m0 + warp_m + mt*16 + lane4;
        #pragma unroll
        for (int nt=0; nt<8; nt++){
            int cg = warp_n + nt*8 + lane2;
            float b0 = g_b2[cg], b1 = g_b2[cg+1];
            float* a4 = acc[mt][nt];
            *(uint32_t*)(O + (size_t)r0*HID + cg)     = pkh2(tanh_fast(a4[0]+b0), tanh_fast(a4[1]+b1));
            *(uint32_t*)(O + (size_t)(r0+8)*HID + cg) = pkh2(tanh_fast(a4[2]+b0), tanh_fast(a4[3]+b1));
        }
    }
}

// ---------------- step 4 fused: nodes 7/8 only, dot out_w, direct store ----------------
__global__ void __launch_bounds__(256,1) step_out_mma(
    const __half* __restrict__ S, const __half* __restrict__ SB,
    const float* __restrict__ out_w, const float* __restrict__ out_b,
    float* __restrict__ out)
{
    extern __shared__ char smraw[];
    uint32_t sb = (smem_u32(smraw) + 1023u) & ~1023u;
    __shared__ float sums[BM];
    const int tid = threadIdx.x, wid = tid>>5, lane = tid&31;
    const int m0 = 7*B_SZ + blockIdx.x * BM;
    const int warp_m = (wid & 1) * 64;
    const int warp_n = (wid >> 1) * 64;

    if (tid < BM) sums[tid] = 0.f;

    float acc[4][8][4];
    #pragma unroll
    for (int a=0;a<4;a++) for (int b=0;b<8;b++) for (int c=0;c<4;c++) acc[a][b][c]=0.f;

    const __half* aS  = S  + (size_t)m0*HID;
    const __half* aSB = SB + (size_t)m0*HID;

    load_stage1(sb,               tid, aS,      HID, g_Wc16,      CATK);
    load_stage1(sb+STG1_BYTES,    tid, aS+BK,   HID, g_Wc16+BK,   CATK);
    load_stage1(sb+2*STG1_BYTES,  tid, aS+2*BK, HID, g_Wc16+2*BK, CATK);

    const int NC = CATK/BK;   // 8
    #pragma unroll 1
    for (int c=0;c<NC;c++){
        pipe_wait(c, NC);
        __syncthreads();
        if (c+3 < NC){
            int s2 = (c+3)%STAGES;
            int kg = (c+3)*BK;
            const __half* aP = (kg < HID ? aS : aSB) + (kg & (HID-1));
            load_stage1(sb + s2*STG1_BYTES, tid, aP, HID, g_Wc16+kg, CATK);
        }
        compute_stage1(sb + (c%STAGES)*STG1_BYTES, acc, warp_m, warp_n, lane);
    }
    __syncthreads();

    const int lane4 = lane>>2, lane2 = (lane&3)*2;
    #pragma unroll
    for (int mt=0; mt<4; mt++){
        int lr0 = warp_m + mt*16 + lane4;
        float p0 = 0.f, p1 = 0.f;
        #pragma unroll
        for (int nt=0; nt<8; nt++){
            int cg = warp_n + nt*8 + lane2;
            float b0 = g_b2[cg], b1 = g_b2[cg+1];
            float w0 = out_w[cg], w1 = out_w[cg+1];
            float* a4 = acc[mt][nt];
            p0 += tanh_fast(a4[0]+b0)*w0 + tanh_fast(a4[1]+b1)*w1;
            p1 += tanh_fast(a4[2]+b0)*w0 + tanh_fast(a4[3]+b1)*w1;
        }
        atomicAdd(&sums[lr0], p0);
        atomicAdd(&sums[lr0+8], p1);
    }
    __syncthreads();
    if (tid < BM){
        int gr = m0 + tid;
        int node = gr >> 14;               // 7 or 8
        int b = gr & (B_SZ-1);
        out[(node-7)*B_SZ + b] = sums[tid] + out_b[0];
    }
}

// ---------------- adjacency aggregate (node-major, uint4) ----------------
__global__ void sbar_kernel(const __half* __restrict__ S, __half* __restrict__ SB)
{
    int idx = blockIdx.x*blockDim.x + threadIdx.x;
    if (idx >= B_SZ*32) return;
    int b = idx>>5, c8 = (idx&31)<<3;
    float s[9][8];
    #pragma unroll
    for (int n=0;n<9;n++){
        uint4 v = *(const uint4*)(S + ((size_t)n*B_SZ + b)*HID + c8);
        float2 f0 = __half22float2(*(__half2*)&v.x);
        float2 f1 = __half22float2(*(__half2*)&v.y);
        float2 f2 = __half22float2(*(__half2*)&v.z);
        float2 f3 = __half22float2(*(__half2*)&v.w);
        s[n][0]=f0.x; s[n][1]=f0.y; s[n][2]=f1.x; s[n][3]=f1.y;
        s[n][4]=f2.x; s[n][5]=f2.y; s[n][6]=f3.x; s[n][7]=f3.y;
    }
    float o[9][8];
    #pragma unroll
    for (int e=0;e<8;e++){
        float tot = 0.f;
        #pragma unroll
        for (int n=0;n<9;n++) tot += s[n][e];
        float hub = s[0][e] + s[7][e] + s[8][e];
        float m78 = (tot - s[1][e]) * 0.125f;
        o[0][e] = tot * (1.f/9.f);
        o[1][e] = (s[0][e] + s[1][e]) * 0.5f;
        #pragma unroll
        for (int n=2;n<=6;n++) o[n][e] = (hub + s[n][e]) * 0.25f;
        o[7][e] = m78; o[8][e] = m78;
    }
    #pragma unroll
    for (int n=0;n<9;n++){
        uint4 w;
        w.x = pkh2(o[n][0],o[n][1]); w.y = pkh2(o[n][2],o[n][3]);
        w.z = pkh2(o[n][4],o[n][5]); w.w = pkh2(o[n][6],o[n][7]);
        *(uint4*)(SB + ((size_t)n*B_SZ + b)*HID + c8) = w;
    }
}

__global__ void sbar78_kernel(const __half* __restrict__ S, __half* __restrict__ SB)
{
    int idx = blockIdx.x*blockDim.x + threadIdx.x;
    if (idx >= B_SZ*32) return;
    int b = idx>>5, c8 = (idx&31)<<3;
    float t[8] = {0,0,0,0,0,0,0,0}, s1[8];
    #pragma unroll
    for (int n=0;n<9;n++){
        uint4 v = *(const uint4*)(S + ((size_t)n*B_SZ + b)*HID + c8);
        float2 f0 = __half22float2(*(__half2*)&v.x);
        float2 f1 = __half22float2(*(__half2*)&v.y);
        float2 f2 = __half22float2(*(__half2*)&v.z);
        float2 f3 = __half22float2(*(__half2*)&v.w);
        float e[8] = {f0.x,f0.y,f1.x,f1.y,f2.x,f2.y,f3.x,f3.y};
        #pragma unroll
        for (int q=0;q<8;q++) t[q] += e[q];
        if (n==1){
            #pragma unroll
            for (int q=0;q<8;q++) s1[q] = e[q];
        }
    }
    uint4 m;
    m.x = pkh2((t[0]-s1[0])*0.125f, (t[1]-s1[1])*0.125f);
    m.y = pkh2((t[2]-s1[2])*0.125f, (t[3]-s1[3])*0.125f);
    m.z = pkh2((t[4]-s1[4])*0.125f, (t[5]-s1[5])*0.125f);
    m.w = pkh2((t[6]-s1[6])*0.125f, (t[7]-s1[7])*0.125f);
    *(uint4*)(SB + ((size_t)7*B_SZ + b)*HID + c8) = m;
    *(uint4*)(SB + ((size_t)8*B_SZ + b)*HID + c8) = m;
}

// ---------------- launch ----------------
extern "C" void kernel_launch(void* const* d_in, const int* in_sizes, int n_in,
                              void* d_out, int out_size)
{
    (void)in_sizes; (void)n_in; (void)out_size;
    const float* conc   = (const float*)d_in[0];
    const float* logits = (const float*)d_in[1];
    const float* enc_w  = (const float*)d_in[2];
    const float* enc_b  = (const float*)d_in[3];
    const float* f2n_w  = (const float*)d_in[4];
    const float* f2n_b  = (const float*)d_in[5];
    const float* msg_w  = (const float*)d_in[6];
    const float* msg_b  = (const float*)d_in[7];
    const float* upd_w  = (const float*)d_in[8];
    const float* upd_b  = (const float*)d_in[9];
    const float* out_w  = (const float*)d_in[10];
    const float* out_b  = (const float*)d_in[11];
    float* out = (float*)d_out;

    __half *a16,*b16,*s0,*s1,*sB;
    cudaGetSymbolAddress((void**)&a16, g_A16);
    cudaGetSymbolAddress((void**)&b16, g_B16);
    cudaGetSymbolAddress((void**)&s0,  g_S0);  cudaGetSymbolAddress((void**)&s1, g_S1);
    cudaGetSymbolAddress((void**)&sB,  g_SB);

    static int smem_set = 0;
    if (!smem_set){
        cudaFuncSetAttribute(gemm1_mma,    cudaFuncAttributeMaxDynamicSharedMemorySize, SMEM1_ALLOC);
        cudaFuncSetAttribute(step_mma,     cudaFuncAttributeMaxDynamicSharedMemorySize, SMEM1_ALLOC);
        cudaFuncSetAttribute(step_out_mma, cudaFuncAttributeMaxDynamicSharedMemorySize, SMEM1_ALLOC);
        smem_set = 1;
    }

    // 0) converts + prep
    conv16_kernel<<<(B_SZ*FDIM/4)/256, 256>>>(conc, a16, B_SZ*FDIM/4);
    conv16_kernel<<<(SDIM*FDIM/4)/256, 256>>>(f2n_w, b16, SDIM*FDIM/4);
    prep_kernel<<<HID, HID>>>(msg_w, msg_b, upd_w, upd_b);

    // 1) big feature GEMM -> S0 (node-major), 1-product fp16
    {
        dim3 grid(NN, B_SZ/BM);   // (9, 128)
        gemm1_mma<<<grid, 256, SMEM1_ALLOC>>>(f2n_b, logits, enc_w, enc_b, s0);
    }

    // 2) steps 1-3 (ping-pong), 1-product fp16
    __half *cur = s0, *nxt = s1;
    for (int step = 0; step < 3; ++step){
        sbar_kernel<<<(B_SZ*32)/256, 256>>>(cur, sB);
        step_mma<<<MROWS/BM, 256, SMEM1_ALLOC>>>(cur, sB, nxt);
        __half* t = cur; cur = nxt; nxt = t;
    }

    // 3) step 4 fused with output head (nodes 7,8 only)
    sbar78_kernel<<<(B_SZ*32)/256, 256>>>(cur, sB);
    step_out_mma<<<2*B_SZ/BM, 256, SMEM1_ALLOC>>>(cur, sB, out_w, out_b, out);
}